// round 2
// baseline (speedup 1.0000x reference)
#include <cuda_runtime.h>
#include <cuda_bf16.h>
#include <math.h>

// ---------------- problem constants ----------------
#define BB 2
#define TT 2048
#define DD 1024
#define HH 16
#define HD 64
#define FF 4096
#define ROWS (BB * TT)          // 4096
#define LN_EPS 1e-5f

// ---------------- scratch (__device__ globals; no allocation) ----------------
__device__ float g_h[ROWS * DD];      // LN1 output
__device__ float g_q[ROWS * DD];
__device__ float g_k[ROWS * DD];
__device__ float g_v[ROWS * DD];
__device__ float g_attn[ROWS * DD];   // attention output (pre-Wo)
__device__ float g_xmid[ROWS * DD];   // x + attn projection
__device__ float g_h2[ROWS * DD];     // LN2 output
__device__ float g_ff[ROWS * FF];     // GELU(h2 @ W1 + b1)
__device__ unsigned char g_mask_u8[TT * TT];  // canonical uint8 mask

// ---------------- mask repack: dtype-agnostic -> uint8 ----------------
// Probe byte 2048: under 1-byte layout it is mask[1][0] == 1 (always true);
// under 4-byte layout (int32/float32) it is LSB of mask[0][512] == 0 (causal).
__global__ __launch_bounds__(256) void mask_repack_kernel(const unsigned char* __restrict__ raw)
{
    int i = blockIdx.x * 256 + threadIdx.x;   // element index, < TT*TT
    bool one_byte = (raw[2048] != 0);
    unsigned char v;
    if (one_byte) {
        v = raw[i];
    } else {
        unsigned int w = ((const unsigned int*)raw)[i];
        v = (w != 0u);
    }
    g_mask_u8[i] = v ? 1 : 0;
}

// ---------------- LayerNorm: one block per row (1024 cols, 256 threads) ----------------
__global__ __launch_bounds__(256) void ln_kernel(const float* __restrict__ x,
                                                 const float* __restrict__ gam,
                                                 const float* __restrict__ bet,
                                                 float* __restrict__ out)
{
    int row = blockIdx.x;
    int t = threadIdx.x;
    const float* xr = x + (size_t)row * DD;
    float4 xv = *(const float4*)(xr + t * 4);
    float s = xv.x + xv.y + xv.z + xv.w;
    __shared__ float red[8];
#pragma unroll
    for (int o = 16; o; o >>= 1) s += __shfl_xor_sync(0xffffffffu, s, o);
    if ((t & 31) == 0) red[t >> 5] = s;
    __syncthreads();
    float mu = 0.f;
#pragma unroll
    for (int i = 0; i < 8; i++) mu += red[i];
    mu *= (1.0f / (float)DD);
    __syncthreads();
    float dx = xv.x - mu, dy = xv.y - mu, dz = xv.z - mu, dw = xv.w - mu;
    float s2 = dx * dx + dy * dy + dz * dz + dw * dw;
#pragma unroll
    for (int o = 16; o; o >>= 1) s2 += __shfl_xor_sync(0xffffffffu, s2, o);
    if ((t & 31) == 0) red[t >> 5] = s2;
    __syncthreads();
    float var = 0.f;
#pragma unroll
    for (int i = 0; i < 8; i++) var += red[i];
    var *= (1.0f / (float)DD);
    float inv = rsqrtf(var + LN_EPS);
    float4 gv = *(const float4*)(gam + t * 4);
    float4 bv = *(const float4*)(bet + t * 4);
    float4 o4;
    o4.x = dx * inv * gv.x + bv.x;
    o4.y = dy * inv * gv.y + bv.y;
    o4.z = dz * inv * gv.z + bv.z;
    o4.w = dw * inv * gv.w + bv.w;
    *(float4*)(out + (size_t)row * DD + t * 4) = o4;
}

// ---------------- SGEMM: C[M,N] = A[M,K] @ W[K,N] (+epilogue) ----------------
// 128x128 tile, BK=16, 256 threads, 8x8 micro-tile.
// EPI: 0 = none, 1 = +bias, 2 = +bias +residual, 3 = +bias then exact GELU
__device__ __forceinline__ float gelu_exact(float x) {
    return 0.5f * x * (1.0f + erff(x * 0.70710678118654752f));
}

template<int EPI>
__global__ __launch_bounds__(256) void gemm_kernel(
    const float* __restrict__ A, const float* __restrict__ W,
    const float* __restrict__ bias, const float* __restrict__ resid,
    float* __restrict__ C, int M, int N, int K)
{
    __shared__ float As[16][132];
    __shared__ float Bs[16][128];
    const int tid = threadIdx.x;
    const int tx = tid & 15, ty = tid >> 4;
    const int mb = blockIdx.y, nb = blockIdx.x;
    const int arow = tid >> 2, ak = (tid & 3) * 4;     // A: 128 rows x 16 cols
    const int brow = tid >> 5, bc = (tid & 31) * 4;    // B: 16 rows x 128 cols
    const float* Ap = A + (size_t)(mb * 128 + arow) * K + ak;
    const float* Bp = W + (size_t)brow * N + nb * 128 + bc;

    float acc[8][8];
#pragma unroll
    for (int i = 0; i < 8; i++)
#pragma unroll
        for (int j = 0; j < 8; j++) acc[i][j] = 0.f;

    for (int k0 = 0; k0 < K; k0 += 16) {
        float4 a0 = *(const float4*)(Ap + k0);
        float4 a1 = *(const float4*)(Ap + (size_t)64 * K + k0);
        float4 b0 = *(const float4*)(Bp + (size_t)k0 * N);
        float4 b1 = *(const float4*)(Bp + (size_t)(k0 + 8) * N);
        __syncthreads();
        As[ak + 0][arow] = a0.x; As[ak + 1][arow] = a0.y;
        As[ak + 2][arow] = a0.z; As[ak + 3][arow] = a0.w;
        As[ak + 0][arow + 64] = a1.x; As[ak + 1][arow + 64] = a1.y;
        As[ak + 2][arow + 64] = a1.z; As[ak + 3][arow + 64] = a1.w;
        *(float4*)&Bs[brow][bc] = b0;
        *(float4*)&Bs[brow + 8][bc] = b1;
        __syncthreads();
#pragma unroll
        for (int kk = 0; kk < 16; kk++) {
            float4 av0 = *(const float4*)&As[kk][ty * 4];
            float4 av1 = *(const float4*)&As[kk][ty * 4 + 64];
            float4 bv0 = *(const float4*)&Bs[kk][tx * 4];
            float4 bv1 = *(const float4*)&Bs[kk][tx * 4 + 64];
            float ar[8] = {av0.x, av0.y, av0.z, av0.w, av1.x, av1.y, av1.z, av1.w};
            float br[8] = {bv0.x, bv0.y, bv0.z, bv0.w, bv1.x, bv1.y, bv1.z, bv1.w};
#pragma unroll
            for (int i = 0; i < 8; i++)
#pragma unroll
                for (int j = 0; j < 8; j++)
                    acc[i][j] = fmaf(ar[i], br[j], acc[i][j]);
        }
    }

#pragma unroll
    for (int i = 0; i < 8; i++) {
        int row = mb * 128 + ((i < 4) ? (ty * 4 + i) : (64 + ty * 4 + i - 4));
#pragma unroll
        for (int jj = 0; jj < 2; jj++) {
            int col = nb * 128 + tx * 4 + jj * 64;
            float v0 = acc[i][jj * 4 + 0], v1 = acc[i][jj * 4 + 1];
            float v2 = acc[i][jj * 4 + 2], v3 = acc[i][jj * 4 + 3];
            if (EPI >= 1) {
                float4 b4 = *(const float4*)(bias + col);
                v0 += b4.x; v1 += b4.y; v2 += b4.z; v3 += b4.w;
            }
            if (EPI == 3) {
                v0 = gelu_exact(v0); v1 = gelu_exact(v1);
                v2 = gelu_exact(v2); v3 = gelu_exact(v3);
            }
            if (EPI == 2) {
                float4 r4 = *(const float4*)(resid + (size_t)row * N + col);
                v0 += r4.x; v1 += r4.y; v2 += r4.z; v3 += r4.w;
            }
            float4 o4; o4.x = v0; o4.y = v1; o4.z = v2; o4.w = v3;
            *(float4*)(C + (size_t)row * N + col) = o4;
        }
    }
}

// ---------------- Flash attention with BigBird mask ----------------
// Block: (q-tile of 64, head, batch). 256 threads (tq=tid/16, tk=tid%16).
// Online softmax over K-tiles of 64; causal tile skipping (kb <= qb).
#define QSI(r, c)  Qs[(r) * 68 + (c)]
#define KPI(r, c)  KPs[(r) * 68 + (c)]
#define VSI(r, c)  Vs[(r) * 68 + (c)]
#define ATTN_SMEM 57088

__global__ __launch_bounds__(256) void attn_kernel(
    const float* __restrict__ Q, const float* __restrict__ Kb,
    const float* __restrict__ Vb, const unsigned char* __restrict__ mask,
    float* __restrict__ O)
{
    extern __shared__ unsigned char sm_raw[];
    float* Qs = (float*)sm_raw;                    // 64*68
    float* KPs = Qs + 64 * 68;                     // K tile, reused as P tile
    float* Vs = KPs + 64 * 68;                     // 64*68
    float* m_s = Vs + 64 * 68;                     // 64
    float* l_s = m_s + 64;                         // 64
    float* al_s = l_s + 64;                        // 64
    unsigned char* Ms = (unsigned char*)(al_s + 64);  // 64*64

    const int qb = blockIdx.x, h = blockIdx.y, bb = blockIdx.z;
    const int tid = threadIdx.x, tq = tid >> 4, tk = tid & 15;
    const int q0 = qb * 64;
    const size_t base = (size_t)bb * TT * DD + (size_t)h * HD;

    // load Q tile (64x64)
#pragma unroll
    for (int i = 0; i < 4; i++) {
        int f = tid + i * 256; int r = f >> 4, c4 = (f & 15) * 4;
        *(float4*)&QSI(r, c4) = *(const float4*)(Q + base + (size_t)(q0 + r) * DD + c4);
    }
    if (tid < 64) { m_s[tid] = -INFINITY; l_s[tid] = 0.f; }

    float acc[4][4];
#pragma unroll
    for (int r = 0; r < 4; r++)
#pragma unroll
        for (int c = 0; c < 4; c++) acc[r][c] = 0.f;

    for (int kb = 0; kb <= qb; kb++) {
        const int k0 = kb * 64;
        __syncthreads();  // prior readers of KPs/Vs/Ms done; first iter: Qs/m_s visible
        // load K, V tiles
#pragma unroll
        for (int i = 0; i < 4; i++) {
            int f = tid + i * 256; int r = f >> 4, c4 = (f & 15) * 4;
            *(float4*)&KPI(r, c4) = *(const float4*)(Kb + base + (size_t)(k0 + r) * DD + c4);
            *(float4*)&VSI(r, c4) = *(const float4*)(Vb + base + (size_t)(k0 + r) * DD + c4);
        }
        // load mask tile (64x64 bytes)
        {
            int r = tid >> 2, seg = tid & 3;
            ((uint4*)Ms)[r * 4 + seg] =
                *(const uint4*)(mask + (size_t)(q0 + r) * TT + k0 + seg * 16);
        }
        __syncthreads();

        // S = Q K^T for micro-tile: rows qi = tq*4+r, cols kk = tk + 16*j
        float s[4][4];
#pragma unroll
        for (int r = 0; r < 4; r++)
#pragma unroll
            for (int j = 0; j < 4; j++) s[r][j] = 0.f;
#pragma unroll
        for (int d4 = 0; d4 < 16; d4++) {
            float4 kv[4];
#pragma unroll
            for (int j = 0; j < 4; j++) kv[j] = *(const float4*)&KPI(tk + 16 * j, d4 * 4);
#pragma unroll
            for (int r = 0; r < 4; r++) {
                float4 qv = *(const float4*)&QSI(tq * 4 + r, d4 * 4);
#pragma unroll
                for (int j = 0; j < 4; j++)
                    s[r][j] = fmaf(qv.x, kv[j].x, fmaf(qv.y, kv[j].y,
                               fmaf(qv.z, kv[j].z, fmaf(qv.w, kv[j].w, s[r][j]))));
            }
        }
        // scale + mask + per-row tile max
        float tmax[4];
#pragma unroll
        for (int r = 0; r < 4; r++) {
            int qi = tq * 4 + r;
#pragma unroll
            for (int j = 0; j < 4; j++) {
                int kk = tk + 16 * j;
                s[r][j] = Ms[qi * 64 + kk] ? s[r][j] * 0.125f : -1e9f;
            }
            float m = fmaxf(fmaxf(s[r][0], s[r][1]), fmaxf(s[r][2], s[r][3]));
#pragma unroll
            for (int o = 8; o; o >>= 1) m = fmaxf(m, __shfl_xor_sync(0xffffffffu, m, o));
            tmax[r] = m;
        }
        if (tk == 0) {
#pragma unroll
            for (int r = 0; r < 4; r++) {
                int qi = tq * 4 + r;
                float mo = m_s[qi];
                float mn = fmaxf(mo, tmax[r]);
                al_s[qi] = __expf(mo - mn);
                m_s[qi] = mn;
            }
        }
        __syncthreads();
        // exp, write P into KPs, update l
#pragma unroll
        for (int r = 0; r < 4; r++) {
            int qi = tq * 4 + r;
            float mrow = m_s[qi];
            float rs = 0.f;
#pragma unroll
            for (int j = 0; j < 4; j++) {
                float p = __expf(s[r][j] - mrow);
                KPI(qi, tk + 16 * j) = p;
                rs += p;
            }
#pragma unroll
            for (int o = 8; o; o >>= 1) rs += __shfl_xor_sync(0xffffffffu, rs, o);
            if (tk == 0) l_s[qi] = l_s[qi] * al_s[qi] + rs;
        }
        __syncthreads();
        // O = alpha*O + P @ V; thread covers qi = tq*4+r, d = tk*4+c
#pragma unroll
        for (int r = 0; r < 4; r++) {
            float a = al_s[tq * 4 + r];
#pragma unroll
            for (int c = 0; c < 4; c++) acc[r][c] *= a;
        }
#pragma unroll
        for (int k4 = 0; k4 < 16; k4++) {
            float4 vv[4];
#pragma unroll
            for (int j = 0; j < 4; j++) vv[j] = *(const float4*)&VSI(k4 * 4 + j, tk * 4);
#pragma unroll
            for (int r = 0; r < 4; r++) {
                float4 p4 = *(const float4*)&KPI(tq * 4 + r, k4 * 4);
                acc[r][0] = fmaf(p4.x, vv[0].x, fmaf(p4.y, vv[1].x,
                             fmaf(p4.z, vv[2].x, fmaf(p4.w, vv[3].x, acc[r][0]))));
                acc[r][1] = fmaf(p4.x, vv[0].y, fmaf(p4.y, vv[1].y,
                             fmaf(p4.z, vv[2].y, fmaf(p4.w, vv[3].y, acc[r][1]))));
                acc[r][2] = fmaf(p4.x, vv[0].z, fmaf(p4.y, vv[1].z,
                             fmaf(p4.z, vv[2].z, fmaf(p4.w, vv[3].z, acc[r][2]))));
                acc[r][3] = fmaf(p4.x, vv[0].w, fmaf(p4.y, vv[1].w,
                             fmaf(p4.z, vv[2].w, fmaf(p4.w, vv[3].w, acc[r][3]))));
            }
        }
    }
    // normalize + write
#pragma unroll
    for (int r = 0; r < 4; r++) {
        int qi = tq * 4 + r;
        float invl = 1.0f / l_s[qi];
        float4 o4;
        o4.x = acc[r][0] * invl; o4.y = acc[r][1] * invl;
        o4.z = acc[r][2] * invl; o4.w = acc[r][3] * invl;
        *(float4*)(O + base + (size_t)(q0 + qi) * DD + tk * 4) = o4;
    }
}

// ---------------- launch ----------------
extern "C" void kernel_launch(void* const* d_in, const int* in_sizes, int n_in,
                              void* d_out, int out_size)
{
    (void)in_sizes; (void)n_in; (void)out_size;
    const float* x     = (const float*)d_in[0];
    const unsigned char* mask_raw = (const unsigned char*)d_in[1];
    const float* ln1_g = (const float*)d_in[2];
    const float* ln1_b = (const float*)d_in[3];
    const float* ln2_g = (const float*)d_in[4];
    const float* ln2_b = (const float*)d_in[5];
    const float* Wq    = (const float*)d_in[6];
    const float* Wk    = (const float*)d_in[7];
    const float* Wv    = (const float*)d_in[8];
    const float* Wo    = (const float*)d_in[9];
    const float* bo    = (const float*)d_in[10];
    const float* W1    = (const float*)d_in[11];
    const float* b1    = (const float*)d_in[12];
    const float* W2    = (const float*)d_in[13];
    const float* b2    = (const float*)d_in[14];
    float* out = (float*)d_out;

    float *h, *q, *k, *v, *attn, *xmid, *h2, *ff;
    unsigned char* mask_u8;
    cudaGetSymbolAddress((void**)&h,    g_h);
    cudaGetSymbolAddress((void**)&q,    g_q);
    cudaGetSymbolAddress((void**)&k,    g_k);
    cudaGetSymbolAddress((void**)&v,    g_v);
    cudaGetSymbolAddress((void**)&attn, g_attn);
    cudaGetSymbolAddress((void**)&xmid, g_xmid);
    cudaGetSymbolAddress((void**)&h2,   g_h2);
    cudaGetSymbolAddress((void**)&ff,   g_ff);
    cudaGetSymbolAddress((void**)&mask_u8, g_mask_u8);

    cudaFuncSetAttribute(attn_kernel, cudaFuncAttributeMaxDynamicSharedMemorySize, ATTN_SMEM);

    // 0) canonicalize mask to uint8 (dtype probe inside kernel)
    mask_repack_kernel<<<(TT * TT) / 256, 256>>>(mask_raw);
    // 1) LN1
    ln_kernel<<<ROWS, 256>>>(x, ln1_g, ln1_b, h);
    // 2) Q,K,V projections
    dim3 g1024(DD / 128, ROWS / 128);
    gemm_kernel<0><<<g1024, 256>>>(h, Wq, nullptr, nullptr, q, ROWS, DD, DD);
    gemm_kernel<0><<<g1024, 256>>>(h, Wk, nullptr, nullptr, k, ROWS, DD, DD);
    gemm_kernel<0><<<g1024, 256>>>(h, Wv, nullptr, nullptr, v, ROWS, DD, DD);
    // 3) attention
    attn_kernel<<<dim3(TT / 64, HH, BB), 256, ATTN_SMEM>>>(q, k, v, mask_u8, attn);
    // 4) Wo projection + bias + residual(x)
    gemm_kernel<2><<<g1024, 256>>>(attn, Wo, bo, x, xmid, ROWS, DD, DD);
    // 5) LN2
    ln_kernel<<<ROWS, 256>>>(xmid, ln2_g, ln2_b, h2);
    // 6) FFN up + GELU
    gemm_kernel<3><<<dim3(FF / 128, ROWS / 128), 256>>>(h2, W1, b1, nullptr, ff, ROWS, FF, DD);
    // 7) FFN down + bias + residual(xmid) -> out
    gemm_kernel<2><<<g1024, 256>>>(ff, W2, b2, xmid, out, ROWS, DD, FF);
}

// round 6
// speedup vs baseline: 1.7681x; 1.7681x over previous
#include <cuda_runtime.h>
#include <math.h>
#include <stdint.h>

// ---------------- problem constants ----------------
#define BB 2
#define TT 2048
#define DD 1024
#define HH 16
#define HD 64
#define FF 4096
#define ROWS (BB * TT)          // 4096
#define LN_EPS 1e-5f

// ---------------- scratch (__device__ globals; no allocation) ----------------
__device__ float g_h[ROWS * DD];
__device__ float g_q[ROWS * DD];
__device__ float g_k[ROWS * DD];
__device__ float g_v[ROWS * DD];
__device__ float g_attn[ROWS * DD];
__device__ float g_xmid[ROWS * DD];
__device__ float g_h2[ROWS * DD];
__device__ float g_ff[ROWS * FF];
__device__ unsigned char g_mask_u8[TT * TT];

// ---------------- helpers ----------------
__device__ __forceinline__ uint32_t f2tf32(float f) {
    uint32_t r;
    asm("cvt.rna.tf32.f32 %0, %1;" : "=r"(r) : "f"(f));
    return r;
}
__device__ __forceinline__ float gelu_exact(float x) {
    return 0.5f * x * (1.0f + erff(x * 0.70710678118654752f));
}
__device__ __forceinline__ void mma_tf32(float c[4], uint32_t a0, uint32_t a1,
                                         uint32_t a2, uint32_t a3,
                                         uint32_t b0, uint32_t b1) {
    asm volatile(
        "mma.sync.aligned.m16n8k8.row.col.f32.tf32.tf32.f32 "
        "{%0,%1,%2,%3}, {%4,%5,%6,%7}, {%8,%9}, {%0,%1,%2,%3};"
        : "+f"(c[0]), "+f"(c[1]), "+f"(c[2]), "+f"(c[3])
        : "r"(a0), "r"(a1), "r"(a2), "r"(a3), "r"(b0), "r"(b1));
}

// ---------------- mask repack: dtype-agnostic -> uint8 ----------------
__global__ __launch_bounds__(256) void mask_repack_kernel(const unsigned char* __restrict__ raw)
{
    int i = blockIdx.x * 256 + threadIdx.x;
    bool one_byte = (raw[2048] != 0);
    unsigned char v;
    if (one_byte) v = raw[i];
    else { unsigned int w = ((const unsigned int*)raw)[i]; v = (w != 0u); }
    g_mask_u8[i] = v ? 1 : 0;
}

// ---------------- LayerNorm ----------------
__global__ __launch_bounds__(256) void ln_kernel(const float* __restrict__ x,
                                                 const float* __restrict__ gam,
                                                 const float* __restrict__ bet,
                                                 float* __restrict__ out)
{
    int row = blockIdx.x;
    int t = threadIdx.x;
    const float* xr = x + (size_t)row * DD;
    float4 xv = *(const float4*)(xr + t * 4);
    float s = xv.x + xv.y + xv.z + xv.w;
    __shared__ float red[8];
#pragma unroll
    for (int o = 16; o; o >>= 1) s += __shfl_xor_sync(0xffffffffu, s, o);
    if ((t & 31) == 0) red[t >> 5] = s;
    __syncthreads();
    float mu = 0.f;
#pragma unroll
    for (int i = 0; i < 8; i++) mu += red[i];
    mu *= (1.0f / (float)DD);
    __syncthreads();
    float dx = xv.x - mu, dy = xv.y - mu, dz = xv.z - mu, dw = xv.w - mu;
    float s2 = dx * dx + dy * dy + dz * dz + dw * dw;
#pragma unroll
    for (int o = 16; o; o >>= 1) s2 += __shfl_xor_sync(0xffffffffu, s2, o);
    if ((t & 31) == 0) red[t >> 5] = s2;
    __syncthreads();
    float var = 0.f;
#pragma unroll
    for (int i = 0; i < 8; i++) var += red[i];
    var *= (1.0f / (float)DD);
    float inv = rsqrtf(var + LN_EPS);
    float4 gv = *(const float4*)(gam + t * 4);
    float4 bv = *(const float4*)(bet + t * 4);
    float4 o4;
    o4.x = dx * inv * gv.x + bv.x;
    o4.y = dy * inv * gv.y + bv.y;
    o4.z = dz * inv * gv.z + bv.z;
    o4.w = dw * inv * gv.w + bv.w;
    *(float4*)(out + (size_t)row * DD + t * 4) = o4;
}

// ---------------- tf32 mma.sync GEMM: C[M,N] = A[M,K] @ W[K,N] (+epilogue) ----------------
// 128x128 CTA tile, 8 warps (2x4), warp tile 64x32 = 4x4 m16n8k8 mmas, BK=16,
// double-buffered smem. EPI: 0 none, 2 = +bias+residual, 3 = +bias then GELU.
#define ASTR 20
#define BSTR 136

template<int EPI>
__global__ __launch_bounds__(256, 2) void mma_gemm(
    const float* __restrict__ A, const float* __restrict__ W,
    const float* __restrict__ bias, const float* __restrict__ resid,
    float* __restrict__ C, int M, int N, int K)
{
    __shared__ uint32_t As[2][128 * ASTR];
    __shared__ uint32_t Bs[2][16 * BSTR];

    const int tid = threadIdx.x;
    const int wid = tid >> 5, lane = tid & 31;
    const int wm = wid & 1, wn = wid >> 1;        // 2 x 4 warps
    const int g = lane >> 2, t = lane & 3;
    const int mb = blockIdx.y, nb = blockIdx.x;

    // gmem load assignment:
    // A: 128 rows x 16 cols; thread -> row tid>>1, col base (tid&1)*8, 2 float4
    // B: 16 rows x 128 cols; thread -> rows (tid>>5) and (tid>>5)+8, col base (tid&31)*4
    const int ar = tid >> 1, ac = (tid & 1) * 8;
    const int br = tid >> 5, bc = (tid & 31) * 4;
    const float* Ap = A + (size_t)(mb * 128 + ar) * K + ac;
    const float* Wp = W + (size_t)br * N + nb * 128 + bc;

    float acc[4][4][4];
#pragma unroll
    for (int i = 0; i < 4; i++)
#pragma unroll
        for (int j = 0; j < 4; j++)
#pragma unroll
            for (int r = 0; r < 4; r++) acc[i][j][r] = 0.f;

    const int NC = K / 16;
    float4 la0, la1, lb0, lb1;

    // prologue: load chunk 0 and store to buf 0
    la0 = *(const float4*)(Ap + 0);
    la1 = *(const float4*)(Ap + 4);
    lb0 = *(const float4*)(Wp);
    lb1 = *(const float4*)(Wp + 8 * (size_t)N);
    {
        uint32_t* as = &As[0][ar * ASTR + ac];
        as[0] = f2tf32(la0.x); as[1] = f2tf32(la0.y); as[2] = f2tf32(la0.z); as[3] = f2tf32(la0.w);
        as[4] = f2tf32(la1.x); as[5] = f2tf32(la1.y); as[6] = f2tf32(la1.z); as[7] = f2tf32(la1.w);
        uint32_t* bs0 = &Bs[0][br * BSTR + bc];
        bs0[0] = f2tf32(lb0.x); bs0[1] = f2tf32(lb0.y); bs0[2] = f2tf32(lb0.z); bs0[3] = f2tf32(lb0.w);
        uint32_t* bs1 = &Bs[0][(br + 8) * BSTR + bc];
        bs1[0] = f2tf32(lb1.x); bs1[1] = f2tf32(lb1.y); bs1[2] = f2tf32(lb1.z); bs1[3] = f2tf32(lb1.w);
    }

    for (int c = 0; c < NC; c++) {
        const int s = c & 1;
        __syncthreads();   // buf s ready (stores from prev iter complete everywhere)
        if (c + 1 < NC) {  // issue gmem loads for next chunk (latency overlapped)
            int k0 = (c + 1) * 16;
            la0 = *(const float4*)(Ap + k0);
            la1 = *(const float4*)(Ap + k0 + 4);
            lb0 = *(const float4*)(Wp + (size_t)k0 * N);
            lb1 = *(const float4*)(Wp + (size_t)(k0 + 8) * N);
        }
        // compute on buf s
        const uint32_t* as = As[s];
        const uint32_t* bs = Bs[s];
#pragma unroll
        for (int ks = 0; ks < 16; ks += 8) {
            uint32_t af[4][4];
#pragma unroll
            for (int mt = 0; mt < 4; mt++) {
                int r0 = wm * 64 + mt * 16 + g;
                af[mt][0] = as[r0 * ASTR + ks + t];
                af[mt][1] = as[(r0 + 8) * ASTR + ks + t];
                af[mt][2] = as[r0 * ASTR + ks + t + 4];
                af[mt][3] = as[(r0 + 8) * ASTR + ks + t + 4];
            }
            uint32_t bf[4][2];
#pragma unroll
            for (int nt = 0; nt < 4; nt++) {
                int cn = wn * 32 + nt * 8 + g;
                bf[nt][0] = bs[(ks + t) * BSTR + cn];
                bf[nt][1] = bs[(ks + t + 4) * BSTR + cn];
            }
#pragma unroll
            for (int mt = 0; mt < 4; mt++)
#pragma unroll
                for (int nt = 0; nt < 4; nt++)
                    mma_tf32(acc[mt][nt], af[mt][0], af[mt][1], af[mt][2], af[mt][3],
                             bf[nt][0], bf[nt][1]);
        }
        // store next chunk to other buffer
        if (c + 1 < NC) {
            const int s1 = s ^ 1;
            uint32_t* asw = &As[s1][ar * ASTR + ac];
            asw[0] = f2tf32(la0.x); asw[1] = f2tf32(la0.y); asw[2] = f2tf32(la0.z); asw[3] = f2tf32(la0.w);
            asw[4] = f2tf32(la1.x); asw[5] = f2tf32(la1.y); asw[6] = f2tf32(la1.z); asw[7] = f2tf32(la1.w);
            uint32_t* bs0 = &Bs[s1][br * BSTR + bc];
            bs0[0] = f2tf32(lb0.x); bs0[1] = f2tf32(lb0.y); bs0[2] = f2tf32(lb0.z); bs0[3] = f2tf32(lb0.w);
            uint32_t* bs1 = &Bs[s1][(br + 8) * BSTR + bc];
            bs1[0] = f2tf32(lb1.x); bs1[1] = f2tf32(lb1.y); bs1[2] = f2tf32(lb1.z); bs1[3] = f2tf32(lb1.w);
        }
    }

    // epilogue
#pragma unroll
    for (int mt = 0; mt < 4; mt++) {
        int row0 = mb * 128 + wm * 64 + mt * 16 + g;
#pragma unroll
        for (int nt = 0; nt < 4; nt++) {
            int col = nb * 128 + wn * 32 + nt * 8 + 2 * t;
#pragma unroll
            for (int half = 0; half < 2; half++) {
                int row = row0 + half * 8;
                float v0 = acc[mt][nt][half * 2 + 0];
                float v1 = acc[mt][nt][half * 2 + 1];
                if (EPI >= 1) { v0 += bias[col]; v1 += bias[col + 1]; }
                if (EPI == 3) { v0 = gelu_exact(v0); v1 = gelu_exact(v1); }
                if (EPI == 2) {
                    const float* rp = resid + (size_t)row * N + col;
                    v0 += rp[0]; v1 += rp[1];
                }
                float2 o2; o2.x = v0; o2.y = v1;
                *(float2*)(C + (size_t)row * N + col) = o2;
            }
        }
    }
}

// ---------------- Flash attention with BigBird mask (fp32) ----------------
#define QSI(r, c)  Qs[(r) * 68 + (c)]
#define KPI(r, c)  KPs[(r) * 68 + (c)]
#define VSI(r, c)  Vs[(r) * 68 + (c)]
#define ATTN_SMEM 57088

__global__ __launch_bounds__(256) void attn_kernel(
    const float* __restrict__ Q, const float* __restrict__ Kb,
    const float* __restrict__ Vb, const unsigned char* __restrict__ mask,
    float* __restrict__ O)
{
    extern __shared__ unsigned char sm_raw[];
    float* Qs = (float*)sm_raw;
    float* KPs = Qs + 64 * 68;
    float* Vs = KPs + 64 * 68;
    float* m_s = Vs + 64 * 68;
    float* l_s = m_s + 64;
    float* al_s = l_s + 64;
    unsigned char* Ms = (unsigned char*)(al_s + 64);

    const int qb = blockIdx.x, h = blockIdx.y, bb = blockIdx.z;
    const int tid = threadIdx.x, tq = tid >> 4, tk = tid & 15;
    const int q0 = qb * 64;
    const size_t base = (size_t)bb * TT * DD + (size_t)h * HD;

#pragma unroll
    for (int i = 0; i < 4; i++) {
        int f = tid + i * 256; int r = f >> 4, c4 = (f & 15) * 4;
        *(float4*)&QSI(r, c4) = *(const float4*)(Q + base + (size_t)(q0 + r) * DD + c4);
    }
    if (tid < 64) { m_s[tid] = -INFINITY; l_s[tid] = 0.f; }

    float acc[4][4];
#pragma unroll
    for (int r = 0; r < 4; r++)
#pragma unroll
        for (int c = 0; c < 4; c++) acc[r][c] = 0.f;

    for (int kb = 0; kb <= qb; kb++) {
        const int k0 = kb * 64;
        __syncthreads();
#pragma unroll
        for (int i = 0; i < 4; i++) {
            int f = tid + i * 256; int r = f >> 4, c4 = (f & 15) * 4;
            *(float4*)&KPI(r, c4) = *(const float4*)(Kb + base + (size_t)(k0 + r) * DD + c4);
            *(float4*)&VSI(r, c4) = *(const float4*)(Vb + base + (size_t)(k0 + r) * DD + c4);
        }
        {
            int r = tid >> 2, seg = tid & 3;
            ((uint4*)Ms)[r * 4 + seg] =
                *(const uint4*)(mask + (size_t)(q0 + r) * TT + k0 + seg * 16);
        }
        __syncthreads();

        float s[4][4];
#pragma unroll
        for (int r = 0; r < 4; r++)
#pragma unroll
            for (int j = 0; j < 4; j++) s[r][j] = 0.f;
#pragma unroll
        for (int d4 = 0; d4 < 16; d4++) {
            float4 kv[4];
#pragma unroll
            for (int j = 0; j < 4; j++) kv[j] = *(const float4*)&KPI(tk + 16 * j, d4 * 4);
#pragma unroll
            for (int r = 0; r < 4; r++) {
                float4 qv = *(const float4*)&QSI(tq * 4 + r, d4 * 4);
#pragma unroll
                for (int j = 0; j < 4; j++)
                    s[r][j] = fmaf(qv.x, kv[j].x, fmaf(qv.y, kv[j].y,
                               fmaf(qv.z, kv[j].z, fmaf(qv.w, kv[j].w, s[r][j]))));
            }
        }
        float tmax[4];
#pragma unroll
        for (int r = 0; r < 4; r++) {
            int qi = tq * 4 + r;
#pragma unroll
            for (int j = 0; j < 4; j++) {
                int kk = tk + 16 * j;
                s[r][j] = Ms[qi * 64 + kk] ? s[r][j] * 0.125f : -1e9f;
            }
            float m = fmaxf(fmaxf(s[r][0], s[r][1]), fmaxf(s[r][2], s[r][3]));
#pragma unroll
            for (int o = 8; o; o >>= 1) m = fmaxf(m, __shfl_xor_sync(0xffffffffu, m, o));
            tmax[r] = m;
        }
        if (tk == 0) {
#pragma unroll
            for (int r = 0; r < 4; r++) {
                int qi = tq * 4 + r;
                float mo = m_s[qi];
                float mn = fmaxf(mo, tmax[r]);
                al_s[qi] = __expf(mo - mn);
                m_s[qi] = mn;
            }
        }
        __syncthreads();
#pragma unroll
        for (int r = 0; r < 4; r++) {
            int qi = tq * 4 + r;
            float mrow = m_s[qi];
            float rs = 0.f;
#pragma unroll
            for (int j = 0; j < 4; j++) {
                float p = __expf(s[r][j] - mrow);
                KPI(qi, tk + 16 * j) = p;
                rs += p;
            }
#pragma unroll
            for (int o = 8; o; o >>= 1) rs += __shfl_xor_sync(0xffffffffu, rs, o);
            if (tk == 0) l_s[qi] = l_s[qi] * al_s[qi] + rs;
        }
        __syncthreads();
#pragma unroll
        for (int r = 0; r < 4; r++) {
            float a = al_s[tq * 4 + r];
#pragma unroll
            for (int c = 0; c < 4; c++) acc[r][c] *= a;
        }
#pragma unroll
        for (int k4 = 0; k4 < 16; k4++) {
            float4 vv[4];
#pragma unroll
            for (int j = 0; j < 4; j++) vv[j] = *(const float4*)&VSI(k4 * 4 + j, tk * 4);
#pragma unroll
            for (int r = 0; r < 4; r++) {
                float4 p4 = *(const float4*)&KPI(tq * 4 + r, k4 * 4);
                acc[r][0] = fmaf(p4.x, vv[0].x, fmaf(p4.y, vv[1].x,
                             fmaf(p4.z, vv[2].x, fmaf(p4.w, vv[3].x, acc[r][0]))));
                acc[r][1] = fmaf(p4.x, vv[0].y, fmaf(p4.y, vv[1].y,
                             fmaf(p4.z, vv[2].y, fmaf(p4.w, vv[3].y, acc[r][1]))));
                acc[r][2] = fmaf(p4.x, vv[0].z, fmaf(p4.y, vv[1].z,
                             fmaf(p4.z, vv[2].z, fmaf(p4.w, vv[3].z, acc[r][2]))));
                acc[r][3] = fmaf(p4.x, vv[0].w, fmaf(p4.y, vv[1].w,
                             fmaf(p4.z, vv[2].w, fmaf(p4.w, vv[3].w, acc[r][3]))));
            }
        }
    }
#pragma unroll
    for (int r = 0; r < 4; r++) {
        int qi = tq * 4 + r;
        float invl = 1.0f / l_s[qi];
        float4 o4;
        o4.x = acc[r][0] * invl; o4.y = acc[r][1] * invl;
        o4.z = acc[r][2] * invl; o4.w = acc[r][3] * invl;
        *(float4*)(O + base + (size_t)(q0 + qi) * DD + tk * 4) = o4;
    }
}

// ---------------- launch ----------------
extern "C" void kernel_launch(void* const* d_in, const int* in_sizes, int n_in,
                              void* d_out, int out_size)
{
    (void)in_sizes; (void)n_in; (void)out_size;
    const float* x     = (const float*)d_in[0];
    const unsigned char* mask_raw = (const unsigned char*)d_in[1];
    const float* ln1_g = (const float*)d_in[2];
    const float* ln1_b = (const float*)d_in[3];
    const float* ln2_g = (const float*)d_in[4];
    const float* ln2_b = (const float*)d_in[5];
    const float* Wq    = (const float*)d_in[6];
    const float* Wk    = (const float*)d_in[7];
    const float* Wv    = (const float*)d_in[8];
    const float* Wo    = (const float*)d_in[9];
    const float* bo    = (const float*)d_in[10];
    const float* W1    = (const float*)d_in[11];
    const float* b1    = (const float*)d_in[12];
    const float* W2    = (const float*)d_in[13];
    const float* b2    = (const float*)d_in[14];
    float* out = (float*)d_out;

    float *h, *q, *k, *v, *attn, *xmid, *h2, *ff;
    unsigned char* mask_u8;
    cudaGetSymbolAddress((void**)&h,    g_h);
    cudaGetSymbolAddress((void**)&q,    g_q);
    cudaGetSymbolAddress((void**)&k,    g_k);
    cudaGetSymbolAddress((void**)&v,    g_v);
    cudaGetSymbolAddress((void**)&attn, g_attn);
    cudaGetSymbolAddress((void**)&xmid, g_xmid);
    cudaGetSymbolAddress((void**)&h2,   g_h2);
    cudaGetSymbolAddress((void**)&ff,   g_ff);
    cudaGetSymbolAddress((void**)&mask_u8, g_mask_u8);

    cudaFuncSetAttribute(attn_kernel, cudaFuncAttributeMaxDynamicSharedMemorySize, ATTN_SMEM);

    // 0) canonicalize mask
    mask_repack_kernel<<<(TT * TT) / 256, 256>>>(mask_raw);
    // 1) LN1
    ln_kernel<<<ROWS, 256>>>(x, ln1_g, ln1_b, h);
    // 2) Q,K,V projections (tf32 mma.sync)
    dim3 g1024(DD / 128, ROWS / 128);
    mma_gemm<0><<<g1024, 256>>>(h, Wq, nullptr, nullptr, q, ROWS, DD, DD);
    mma_gemm<0><<<g1024, 256>>>(h, Wk, nullptr, nullptr, k, ROWS, DD, DD);
    mma_gemm<0><<<g1024, 256>>>(h, Wv, nullptr, nullptr, v, ROWS, DD, DD);
    // 3) attention
    attn_kernel<<<dim3(TT / 64, HH, BB), 256, ATTN_SMEM>>>(q, k, v, mask_u8, attn);
    // 4) Wo + bias + residual(x)
    mma_gemm<2><<<g1024, 256>>>(attn, Wo, bo, x, xmid, ROWS, DD, DD);
    // 5) LN2
    ln_kernel<<<ROWS, 256>>>(xmid, ln2_g, ln2_b, h2);
    // 6) FFN up + GELU
    mma_gemm<3><<<dim3(FF / 128, ROWS / 128), 256>>>(h2, W1, b1, nullptr, ff, ROWS, FF, DD);
    // 7) FFN down + bias + residual(xmid) -> out
    mma_gemm<2><<<g1024, 256>>>(ff, W2, b2, xmid, out, ROWS, DD, FF);
}

// round 7
// speedup vs baseline: 2.2815x; 1.2904x over previous
#include <cuda_runtime.h>
#include <math.h>
#include <stdint.h>

// ---------------- problem constants ----------------
#define BB 2
#define TT 2048
#define DD 1024
#define HH 16
#define HD 64
#define FF 4096
#define ROWS (BB * TT)          // 4096
#define LN_EPS 1e-5f

// ---------------- scratch (__device__ globals; no allocation) ----------------
__device__ float g_h[ROWS * DD];
__device__ float g_q[ROWS * DD];
__device__ float g_k[ROWS * DD];
__device__ float g_v[ROWS * DD];
__device__ float g_attn[ROWS * DD];
__device__ float g_xmid[ROWS * DD];
__device__ float g_h2[ROWS * DD];
__device__ float g_ff[ROWS * FF];
__device__ unsigned char g_mask_u8[TT * TT];
// transposed (n-major, k-contiguous) tf32-rounded weights
__device__ float g_wqt[DD * DD];
__device__ float g_wkt[DD * DD];
__device__ float g_wvt[DD * DD];
__device__ float g_wot[DD * DD];
__device__ float g_w1t[FF * DD];   // [4096][1024]
__device__ float g_w2t[DD * FF];   // [1024][4096]

// ---------------- helpers ----------------
__device__ __forceinline__ uint32_t f2tf32(float f) {
    uint32_t r;
    asm("cvt.rna.tf32.f32 %0, %1;" : "=r"(r) : "f"(f));
    return r;
}
__device__ __forceinline__ float gelu_exact(float x) {
    return 0.5f * x * (1.0f + erff(x * 0.70710678118654752f));
}
__device__ __forceinline__ void mma_tf32(float c[4], uint32_t a0, uint32_t a1,
                                         uint32_t a2, uint32_t a3,
                                         uint32_t b0, uint32_t b1) {
    asm volatile(
        "mma.sync.aligned.m16n8k8.row.col.f32.tf32.tf32.f32 "
        "{%0,%1,%2,%3}, {%4,%5,%6,%7}, {%8,%9}, {%0,%1,%2,%3};"
        : "+f"(c[0]), "+f"(c[1]), "+f"(c[2]), "+f"(c[3])
        : "r"(a0), "r"(a1), "r"(a2), "r"(a3), "r"(b0), "r"(b1));
}
__device__ __forceinline__ void ldsm_x4(uint32_t& r0, uint32_t& r1,
                                        uint32_t& r2, uint32_t& r3, uint32_t addr) {
    asm volatile("ldmatrix.sync.aligned.m8n8.x4.shared.b16 {%0,%1,%2,%3}, [%4];"
                 : "=r"(r0), "=r"(r1), "=r"(r2), "=r"(r3) : "r"(addr));
}
__device__ __forceinline__ void cp_async16(uint32_t saddr, const float* gaddr) {
    asm volatile("cp.async.cg.shared.global [%0], [%1], 16;" :: "r"(saddr), "l"(gaddr));
}
#define CP_COMMIT() asm volatile("cp.async.commit_group;" ::: "memory")
#define CP_WAIT1() asm volatile("cp.async.wait_group 1;" ::: "memory")
#define CP_WAIT0() asm volatile("cp.async.wait_group 0;" ::: "memory")

// ---------------- mask repack: dtype-agnostic -> uint8 ----------------
__global__ __launch_bounds__(256) void mask_repack_kernel(const unsigned char* __restrict__ raw)
{
    int i = blockIdx.x * 256 + threadIdx.x;
    bool one_byte = (raw[2048] != 0);
    unsigned char v;
    if (one_byte) v = raw[i];
    else { unsigned int w = ((const unsigned int*)raw)[i]; v = (w != 0u); }
    g_mask_u8[i] = v ? 1 : 0;
}

// ---------------- weight transpose (+rna tf32 round): dst[c][r] = tf32(src[r][c]) ----------------
__global__ __launch_bounds__(256) void transpose_kernel(const float* __restrict__ src,
                                                        float* __restrict__ dst,
                                                        int R, int C)
{
    __shared__ float t[32][33];
    int c0 = blockIdx.x * 32, r0 = blockIdx.y * 32;
    int tx = threadIdx.x & 31, ty = threadIdx.x >> 5;   // 32x8
#pragma unroll
    for (int i = 0; i < 32; i += 8)
        t[ty + i][tx] = src[(size_t)(r0 + ty + i) * C + c0 + tx];
    __syncthreads();
#pragma unroll
    for (int i = 0; i < 32; i += 8)
        dst[(size_t)(c0 + ty + i) * R + r0 + tx] = __uint_as_float(f2tf32(t[tx][ty + i]));
}

// ---------------- LayerNorm ----------------
__global__ __launch_bounds__(256) void ln_kernel(const float* __restrict__ x,
                                                 const float* __restrict__ gam,
                                                 const float* __restrict__ bet,
                                                 float* __restrict__ out)
{
    int row = blockIdx.x;
    int t = threadIdx.x;
    const float* xr = x + (size_t)row * DD;
    float4 xv = *(const float4*)(xr + t * 4);
    float s = xv.x + xv.y + xv.z + xv.w;
    __shared__ float red[8];
#pragma unroll
    for (int o = 16; o; o >>= 1) s += __shfl_xor_sync(0xffffffffu, s, o);
    if ((t & 31) == 0) red[t >> 5] = s;
    __syncthreads();
    float mu = 0.f;
#pragma unroll
    for (int i = 0; i < 8; i++) mu += red[i];
    mu *= (1.0f / (float)DD);
    __syncthreads();
    float dx = xv.x - mu, dy = xv.y - mu, dz = xv.z - mu, dw = xv.w - mu;
    float s2 = dx * dx + dy * dy + dz * dz + dw * dw;
#pragma unroll
    for (int o = 16; o; o >>= 1) s2 += __shfl_xor_sync(0xffffffffu, s2, o);
    if ((t & 31) == 0) red[t >> 5] = s2;
    __syncthreads();
    float var = 0.f;
#pragma unroll
    for (int i = 0; i < 8; i++) var += red[i];
    var *= (1.0f / (float)DD);
    float inv = rsqrtf(var + LN_EPS);
    float4 gv = *(const float4*)(gam + t * 4);
    float4 bv = *(const float4*)(bet + t * 4);
    float4 o4;
    o4.x = dx * inv * gv.x + bv.x;
    o4.y = dy * inv * gv.y + bv.y;
    o4.z = dz * inv * gv.z + bv.z;
    o4.w = dw * inv * gv.w + bv.w;
    *(float4*)(out + (size_t)row * DD + t * 4) = o4;
}

// ---------------- tf32 mma.sync GEMM: C[M,N] = A[M,K] @ Bt[N,K]^T (+epilogue) ----
// CTA 128x128, 4 warps (2x2), warp tile 64x64 = 4x8 m16n8k8 tiles, BK=32,
// 3-stage cp.async pipeline, ldmatrix.x4 fragment loads, XOR-16B swizzled smem.
// A: raw fp32 (HW tf32 truncation). Bt: pre-rounded (rna) n-major weights.
// EPI: 0 none, 2 = +bias+residual, 3 = +bias then GELU.
#define GSTAGE 32768
#define GSMEM  (3 * GSTAGE)

template<int EPI>
__global__ __launch_bounds__(128, 2) void mma_gemm(
    const float* __restrict__ A, const float* __restrict__ Bt,
    const float* __restrict__ bias, const float* __restrict__ resid,
    float* __restrict__ C, int M, int N, int K)
{
    extern __shared__ unsigned char smem_raw[];
    const uint32_t sbase = (uint32_t)__cvta_generic_to_shared(smem_raw);
    const int tid = threadIdx.x;
    const int wid = tid >> 5, lane = tid & 31;
    const int wm = wid & 1, wn = wid >> 1;          // 2 x 2 warps
    const int g = lane >> 2, t = lane & 3;
    const int mb = blockIdx.y, nb = blockIdx.x;

    // cp.async per-thread constants: 16 rows of 16B chunks per pass
    const int rl = tid >> 3;                        // 0..15
    const int ch = tid & 7;                         // 0..7 (16B chunk in row)
    const uint32_t sw16 = (uint32_t)((ch ^ (rl & 7)) * 16);
    const float* Ag = A + (size_t)(mb * 128 + rl) * K + ch * 4;
    const float* Bg = Bt + (size_t)(nb * 128 + rl) * K + ch * 4;

    // ldmatrix per-lane constants
    const int l7 = lane & 7, mat = lane >> 3;
    const uint32_t a_rp = (uint32_t)((l7 + (mat & 1) * 8) * 128);
    const int a_ca = mat >> 1;
    const uint32_t b_rp = (uint32_t)((l7 + (mat >> 1) * 8) * 128);
    const int b_ca = mat & 1;

    float acc[4][8][4];
#pragma unroll
    for (int i = 0; i < 4; i++)
#pragma unroll
        for (int j = 0; j < 8; j++)
#pragma unroll
            for (int r = 0; r < 4; r++) acc[i][j][r] = 0.f;

    const int NC = K / 32;

    auto issue = [&](int cc, int s) {
        const uint32_t ab = sbase + (uint32_t)s * GSTAGE;
        const size_t ko = (size_t)cc * 32;
#pragma unroll
        for (int p = 0; p < 8; p++) {
            uint32_t soff = (uint32_t)((p * 16 + rl) * 128) + sw16;
            cp_async16(ab + soff,          Ag + (size_t)(p * 16) * K + ko);
            cp_async16(ab + 16384u + soff, Bg + (size_t)(p * 16) * K + ko);
        }
        CP_COMMIT();
    };

    issue(0, 0);
    issue(1, 1);

    for (int c = 0; c < NC; c++) {
        if (c < NC - 1) { CP_WAIT1(); } else { CP_WAIT0(); }
        __syncthreads();                 // stage c visible to all; stage (c-1) buffers free
        if (c + 2 < NC) issue(c + 2, (c + 2) % 3);

        const uint32_t sa = sbase + (uint32_t)(c % 3) * GSTAGE;
        const uint32_t sb = sa + 16384u;
#pragma unroll
        for (int ks = 0; ks < 4; ks++) {
            const int c0 = ks * 2;
            uint32_t af[4][4];
#pragma unroll
            for (int mt = 0; mt < 4; mt++) {
                uint32_t addr = sa + (uint32_t)((wm * 64 + mt * 16) * 128) + a_rp
                              + (uint32_t)(((c0 + a_ca) ^ l7) * 16);
                ldsm_x4(af[mt][0], af[mt][1], af[mt][2], af[mt][3], addr);
            }
            uint32_t bf[8][2];
#pragma unroll
            for (int pr = 0; pr < 4; pr++) {
                uint32_t addr = sb + (uint32_t)((wn * 64 + pr * 16) * 128) + b_rp
                              + (uint32_t)(((c0 + b_ca) ^ l7) * 16);
                ldsm_x4(bf[2 * pr][0], bf[2 * pr][1], bf[2 * pr + 1][0], bf[2 * pr + 1][1], addr);
            }
#pragma unroll
            for (int mt = 0; mt < 4; mt++)
#pragma unroll
                for (int nt = 0; nt < 8; nt++)
                    mma_tf32(acc[mt][nt], af[mt][0], af[mt][1], af[mt][2], af[mt][3],
                             bf[nt][0], bf[nt][1]);
        }
    }

    // epilogue
#pragma unroll
    for (int mt = 0; mt < 4; mt++) {
        int row0 = mb * 128 + wm * 64 + mt * 16 + g;
#pragma unroll
        for (int nt = 0; nt < 8; nt++) {
            int col = nb * 128 + wn * 64 + nt * 8 + 2 * t;
#pragma unroll
            for (int half = 0; half < 2; half++) {
                int row = row0 + half * 8;
                float v0 = acc[mt][nt][half * 2 + 0];
                float v1 = acc[mt][nt][half * 2 + 1];
                if (EPI >= 1) { v0 += bias[col]; v1 += bias[col + 1]; }
                if (EPI == 3) { v0 = gelu_exact(v0); v1 = gelu_exact(v1); }
                if (EPI == 2) {
                    const float* rp = resid + (size_t)row * N + col;
                    v0 += rp[0]; v1 += rp[1];
                }
                float2 o2; o2.x = v0; o2.y = v1;
                *(float2*)(C + (size_t)row * N + col) = o2;
            }
        }
    }
}

// ---------------- Flash attention with BigBird mask (fp32) ----------------
#define QSI(r, c)  Qs[(r) * 68 + (c)]
#define KPI(r, c)  KPs[(r) * 68 + (c)]
#define VSI(r, c)  Vs[(r) * 68 + (c)]
#define ATTN_SMEM 57088

__global__ __launch_bounds__(256) void attn_kernel(
    const float* __restrict__ Q, const float* __restrict__ Kb,
    const float* __restrict__ Vb, const unsigned char* __restrict__ mask,
    float* __restrict__ O)
{
    extern __shared__ unsigned char sm_raw[];
    float* Qs = (float*)sm_raw;
    float* KPs = Qs + 64 * 68;
    float* Vs = KPs + 64 * 68;
    float* m_s = Vs + 64 * 68;
    float* l_s = m_s + 64;
    float* al_s = l_s + 64;
    unsigned char* Ms = (unsigned char*)(al_s + 64);

    const int qb = blockIdx.x, h = blockIdx.y, bb = blockIdx.z;
    const int tid = threadIdx.x, tq = tid >> 4, tk = tid & 15;
    const int q0 = qb * 64;
    const size_t base = (size_t)bb * TT * DD + (size_t)h * HD;

#pragma unroll
    for (int i = 0; i < 4; i++) {
        int f = tid + i * 256; int r = f >> 4, c4 = (f & 15) * 4;
        *(float4*)&QSI(r, c4) = *(const float4*)(Q + base + (size_t)(q0 + r) * DD + c4);
    }
    if (tid < 64) { m_s[tid] = -INFINITY; l_s[tid] = 0.f; }

    float acc[4][4];
#pragma unroll
    for (int r = 0; r < 4; r++)
#pragma unroll
        for (int c = 0; c < 4; c++) acc[r][c] = 0.f;

    for (int kb = 0; kb <= qb; kb++) {
        const int k0 = kb * 64;
        __syncthreads();
#pragma unroll
        for (int i = 0; i < 4; i++) {
            int f = tid + i * 256; int r = f >> 4, c4 = (f & 15) * 4;
            *(float4*)&KPI(r, c4) = *(const float4*)(Kb + base + (size_t)(k0 + r) * DD + c4);
            *(float4*)&VSI(r, c4) = *(const float4*)(Vb + base + (size_t)(k0 + r) * DD + c4);
        }
        {
            int r = tid >> 2, seg = tid & 3;
            ((uint4*)Ms)[r * 4 + seg] =
                *(const uint4*)(mask + (size_t)(q0 + r) * TT + k0 + seg * 16);
        }
        __syncthreads();

        float s[4][4];
#pragma unroll
        for (int r = 0; r < 4; r++)
#pragma unroll
            for (int j = 0; j < 4; j++) s[r][j] = 0.f;
#pragma unroll
        for (int d4 = 0; d4 < 16; d4++) {
            float4 kv[4];
#pragma unroll
            for (int j = 0; j < 4; j++) kv[j] = *(const float4*)&KPI(tk + 16 * j, d4 * 4);
#pragma unroll
            for (int r = 0; r < 4; r++) {
                float4 qv = *(const float4*)&QSI(tq * 4 + r, d4 * 4);
#pragma unroll
                for (int j = 0; j < 4; j++)
                    s[r][j] = fmaf(qv.x, kv[j].x, fmaf(qv.y, kv[j].y,
                               fmaf(qv.z, kv[j].z, fmaf(qv.w, kv[j].w, s[r][j]))));
            }
        }
        float tmax[4];
#pragma unroll
        for (int r = 0; r < 4; r++) {
            int qi = tq * 4 + r;
#pragma unroll
            for (int j = 0; j < 4; j++) {
                int kk = tk + 16 * j;
                s[r][j] = Ms[qi * 64 + kk] ? s[r][j] * 0.125f : -1e9f;
            }
            float m = fmaxf(fmaxf(s[r][0], s[r][1]), fmaxf(s[r][2], s[r][3]));
#pragma unroll
            for (int o = 8; o; o >>= 1) m = fmaxf(m, __shfl_xor_sync(0xffffffffu, m, o));
            tmax[r] = m;
        }
        if (tk == 0) {
#pragma unroll
            for (int r = 0; r < 4; r++) {
                int qi = tq * 4 + r;
                float mo = m_s[qi];
                float mn = fmaxf(mo, tmax[r]);
                al_s[qi] = __expf(mo - mn);
                m_s[qi] = mn;
            }
        }
        __syncthreads();
#pragma unroll
        for (int r = 0; r < 4; r++) {
            int qi = tq * 4 + r;
            float mrow = m_s[qi];
            float rs = 0.f;
#pragma unroll
            for (int j = 0; j < 4; j++) {
                float p = __expf(s[r][j] - mrow);
                KPI(qi, tk + 16 * j) = p;
                rs += p;
            }
#pragma unroll
            for (int o = 8; o; o >>= 1) rs += __shfl_xor_sync(0xffffffffu, rs, o);
            if (tk == 0) l_s[qi] = l_s[qi] * al_s[qi] + rs;
        }
        __syncthreads();
#pragma unroll
        for (int r = 0; r < 4; r++) {
            float a = al_s[tq * 4 + r];
#pragma unroll
            for (int c = 0; c < 4; c++) acc[r][c] *= a;
        }
#pragma unroll
        for (int k4 = 0; k4 < 16; k4++) {
            float4 vv[4];
#pragma unroll
            for (int j = 0; j < 4; j++) vv[j] = *(const float4*)&VSI(k4 * 4 + j, tk * 4);
#pragma unroll
            for (int r = 0; r < 4; r++) {
                float4 p4 = *(const float4*)&KPI(tq * 4 + r, k4 * 4);
                acc[r][0] = fmaf(p4.x, vv[0].x, fmaf(p4.y, vv[1].x,
                             fmaf(p4.z, vv[2].x, fmaf(p4.w, vv[3].x, acc[r][0]))));
                acc[r][1] = fmaf(p4.x, vv[0].y, fmaf(p4.y, vv[1].y,
                             fmaf(p4.z, vv[2].y, fmaf(p4.w, vv[3].y, acc[r][1]))));
                acc[r][2] = fmaf(p4.x, vv[0].z, fmaf(p4.y, vv[1].z,
                             fmaf(p4.z, vv[2].z, fmaf(p4.w, vv[3].z, acc[r][2]))));
                acc[r][3] = fmaf(p4.x, vv[0].w, fmaf(p4.y, vv[1].w,
                             fmaf(p4.z, vv[2].w, fmaf(p4.w, vv[3].w, acc[r][3]))));
            }
        }
    }
#pragma unroll
    for (int r = 0; r < 4; r++) {
        int qi = tq * 4 + r;
        float invl = 1.0f / l_s[qi];
        float4 o4;
        o4.x = acc[r][0] * invl; o4.y = acc[r][1] * invl;
        o4.z = acc[r][2] * invl; o4.w = acc[r][3] * invl;
        *(float4*)(O + base + (size_t)(q0 + qi) * DD + tk * 4) = o4;
    }
}

// ---------------- launch ----------------
extern "C" void kernel_launch(void* const* d_in, const int* in_sizes, int n_in,
                              void* d_out, int out_size)
{
    (void)in_sizes; (void)n_in; (void)out_size;
    const float* x     = (const float*)d_in[0];
    const unsigned char* mask_raw = (const unsigned char*)d_in[1];
    const float* ln1_g = (const float*)d_in[2];
    const float* ln1_b = (const float*)d_in[3];
    const float* ln2_g = (const float*)d_in[4];
    const float* ln2_b = (const float*)d_in[5];
    const float* Wq    = (const float*)d_in[6];
    const float* Wk    = (const float*)d_in[7];
    const float* Wv    = (const float*)d_in[8];
    const float* Wo    = (const float*)d_in[9];
    const float* bo    = (const float*)d_in[10];
    const float* W1    = (const float*)d_in[11];
    const float* b1    = (const float*)d_in[12];
    const float* W2    = (const float*)d_in[13];
    const float* b2    = (const float*)d_in[14];
    float* out = (float*)d_out;

    float *h, *q, *k, *v, *attn, *xmid, *h2, *ff;
    float *wqt, *wkt, *wvt, *wot, *w1t, *w2t;
    unsigned char* mask_u8;
    cudaGetSymbolAddress((void**)&h,    g_h);
    cudaGetSymbolAddress((void**)&q,    g_q);
    cudaGetSymbolAddress((void**)&k,    g_k);
    cudaGetSymbolAddress((void**)&v,    g_v);
    cudaGetSymbolAddress((void**)&attn, g_attn);
    cudaGetSymbolAddress((void**)&xmid, g_xmid);
    cudaGetSymbolAddress((void**)&h2,   g_h2);
    cudaGetSymbolAddress((void**)&ff,   g_ff);
    cudaGetSymbolAddress((void**)&wqt,  g_wqt);
    cudaGetSymbolAddress((void**)&wkt,  g_wkt);
    cudaGetSymbolAddress((void**)&wvt,  g_wvt);
    cudaGetSymbolAddress((void**)&wot,  g_wot);
    cudaGetSymbolAddress((void**)&w1t,  g_w1t);
    cudaGetSymbolAddress((void**)&w2t,  g_w2t);
    cudaGetSymbolAddress((void**)&mask_u8, g_mask_u8);

    cudaFuncSetAttribute(attn_kernel, cudaFuncAttributeMaxDynamicSharedMemorySize, ATTN_SMEM);
    cudaFuncSetAttribute(mma_gemm<0>, cudaFuncAttributeMaxDynamicSharedMemorySize, GSMEM);
    cudaFuncSetAttribute(mma_gemm<2>, cudaFuncAttributeMaxDynamicSharedMemorySize, GSMEM);
    cudaFuncSetAttribute(mma_gemm<3>, cudaFuncAttributeMaxDynamicSharedMemorySize, GSMEM);

    // 0) canonicalize mask + transpose weights to n-major (rna tf32)
    mask_repack_kernel<<<(TT * TT) / 256, 256>>>(mask_raw);
    transpose_kernel<<<dim3(DD / 32, DD / 32), 256>>>(Wq, wqt, DD, DD);
    transpose_kernel<<<dim3(DD / 32, DD / 32), 256>>>(Wk, wkt, DD, DD);
    transpose_kernel<<<dim3(DD / 32, DD / 32), 256>>>(Wv, wvt, DD, DD);
    transpose_kernel<<<dim3(DD / 32, DD / 32), 256>>>(Wo, wot, DD, DD);
    transpose_kernel<<<dim3(FF / 32, DD / 32), 256>>>(W1, w1t, DD, FF);
    transpose_kernel<<<dim3(DD / 32, FF / 32), 256>>>(W2, w2t, FF, DD);
    // 1) LN1
    ln_kernel<<<ROWS, 256>>>(x, ln1_g, ln1_b, h);
    // 2) Q,K,V projections
    dim3 g1024(DD / 128, ROWS / 128);
    mma_gemm<0><<<g1024, 128, GSMEM>>>(h, wqt, nullptr, nullptr, q, ROWS, DD, DD);
    mma_gemm<0><<<g1024, 128, GSMEM>>>(h, wkt, nullptr, nullptr, k, ROWS, DD, DD);
    mma_gemm<0><<<g1024, 128, GSMEM>>>(h, wvt, nullptr, nullptr, v, ROWS, DD, DD);
    // 3) attention
    attn_kernel<<<dim3(TT / 64, HH, BB), 256, ATTN_SMEM>>>(q, k, v, mask_u8, attn);
    // 4) Wo + bias + residual(x)
    mma_gemm<2><<<g1024, 128, GSMEM>>>(attn, wot, bo, x, xmid, ROWS, DD, DD);
    // 5) LN2
    ln_kernel<<<ROWS, 256>>>(xmid, ln2_g, ln2_b, h2);
    // 6) FFN up + GELU
    mma_gemm<3><<<dim3(FF / 128, ROWS / 128), 128, GSMEM>>>(h2, w1t, b1, nullptr, ff, ROWS, FF, DD);
    // 7) FFN down + bias + residual(xmid) -> out
    mma_gemm<2><<<g1024, 128, GSMEM>>>(ff, w2t, b2, xmid, out, ROWS, DD, FF);
}

// round 8
// speedup vs baseline: 3.0397x; 1.3323x over previous
#include <cuda_runtime.h>
#include <math.h>
#include <stdint.h>

// ---------------- problem constants ----------------
#define BB 2
#define TT 2048
#define DD 1024
#define HH 16
#define HD 64
#define FF 4096
#define ROWS (BB * TT)          // 4096
#define LN_EPS 1e-5f

// ---------------- scratch (__device__ globals; no allocation) ----------------
__device__ float g_h[ROWS * DD];
__device__ float g_q[ROWS * DD];
__device__ float g_k[ROWS * DD];
__device__ float g_v[ROWS * DD];
__device__ float g_vt[BB * HH * HD * TT];   // [b,h][d][t]
__device__ float g_attn[ROWS * DD];
__device__ float g_xmid[ROWS * DD];
__device__ float g_h2[ROWS * DD];
__device__ float g_ff[ROWS * FF];
__device__ unsigned long long g_mask_bits[TT * (TT / 64)];
// transposed (n-major, k-contiguous) tf32-rounded weights
__device__ float g_wqt[DD * DD];
__device__ float g_wkt[DD * DD];
__device__ float g_wvt[DD * DD];
__device__ float g_wot[DD * DD];
__device__ float g_w1t[FF * DD];
__device__ float g_w2t[DD * FF];

// ---------------- helpers ----------------
__device__ __forceinline__ uint32_t f2tf32(float f) {
    uint32_t r;
    asm("cvt.rna.tf32.f32 %0, %1;" : "=r"(r) : "f"(f));
    return r;
}
__device__ __forceinline__ float gelu_exact(float x) {
    return 0.5f * x * (1.0f + erff(x * 0.70710678118654752f));
}
__device__ __forceinline__ void mma_tf32(float c[4], uint32_t a0, uint32_t a1,
                                         uint32_t a2, uint32_t a3,
                                         uint32_t b0, uint32_t b1) {
    asm volatile(
        "mma.sync.aligned.m16n8k8.row.col.f32.tf32.tf32.f32 "
        "{%0,%1,%2,%3}, {%4,%5,%6,%7}, {%8,%9}, {%0,%1,%2,%3};"
        : "+f"(c[0]), "+f"(c[1]), "+f"(c[2]), "+f"(c[3])
        : "r"(a0), "r"(a1), "r"(a2), "r"(a3), "r"(b0), "r"(b1));
}
__device__ __forceinline__ void ldsm_x4(uint32_t& r0, uint32_t& r1,
                                        uint32_t& r2, uint32_t& r3, uint32_t addr) {
    asm volatile("ldmatrix.sync.aligned.m8n8.x4.shared.b16 {%0,%1,%2,%3}, [%4];"
                 : "=r"(r0), "=r"(r1), "=r"(r2), "=r"(r3) : "r"(addr));
}
__device__ __forceinline__ void cp_async16(uint32_t saddr, const float* gaddr) {
    asm volatile("cp.async.cg.shared.global [%0], [%1], 16;" :: "r"(saddr), "l"(gaddr));
}
#define CP_COMMIT() asm volatile("cp.async.commit_group;" ::: "memory")
#define CP_WAIT1() asm volatile("cp.async.wait_group 1;" ::: "memory")
#define CP_WAIT0() asm volatile("cp.async.wait_group 0;" ::: "memory")
__device__ __forceinline__ void sts64(uint32_t addr, float a, float b) {
    asm volatile("st.shared.v2.f32 [%0], {%1,%2};" :: "r"(addr), "f"(a), "f"(b));
}

// ---------------- mask repack: dtype-agnostic -> 64-bit rows ----------------
__global__ __launch_bounds__(256) void mask_bits_kernel(const unsigned char* __restrict__ raw)
{
    int i = blockIdx.x * 256 + threadIdx.x;    // word index < TT*32
    int row = i >> 5, w = i & 31;
    bool one_byte = (raw[2048] != 0);
    unsigned long long bits = 0ull;
    if (one_byte) {
        const unsigned char* p = raw + (size_t)row * TT + w * 64;
#pragma unroll 8
        for (int j = 0; j < 64; j++) if (p[j]) bits |= 1ull << j;
    } else {
        const unsigned int* p = (const unsigned int*)raw + (size_t)row * TT + w * 64;
#pragma unroll 8
        for (int j = 0; j < 64; j++) if (p[j]) bits |= 1ull << j;
    }
    g_mask_bits[i] = bits;
}

// ---------------- weight transpose (+rna tf32 round) ----------------
__global__ __launch_bounds__(256) void transpose_kernel(const float* __restrict__ src,
                                                        float* __restrict__ dst,
                                                        int R, int C)
{
    __shared__ float t[32][33];
    int c0 = blockIdx.x * 32, r0 = blockIdx.y * 32;
    int tx = threadIdx.x & 31, ty = threadIdx.x >> 5;
#pragma unroll
    for (int i = 0; i < 32; i += 8)
        t[ty + i][tx] = src[(size_t)(r0 + ty + i) * C + c0 + tx];
    __syncthreads();
#pragma unroll
    for (int i = 0; i < 32; i += 8)
        dst[(size_t)(c0 + ty + i) * R + r0 + tx] = __uint_as_float(f2tf32(t[tx][ty + i]));
}

// ---------------- V transpose per head: vt[b,h][d][t] = v[b][t][h*64+d] ----------------
__global__ __launch_bounds__(256) void vtrans_kernel(const float* __restrict__ v,
                                                     float* __restrict__ vt)
{
    __shared__ float tsh[32][33];
    int bh = blockIdx.z;
    int b = bh >> 4, h = bh & 15;
    int t0 = blockIdx.x * 32, d0 = blockIdx.y * 32;
    int tx = threadIdx.x & 31, ty = threadIdx.x >> 5;
    const float* src = v + (size_t)b * TT * DD + (size_t)h * HD;
#pragma unroll
    for (int i = 0; i < 32; i += 8)
        tsh[ty + i][tx] = src[(size_t)(t0 + ty + i) * DD + d0 + tx];
    __syncthreads();
    float* dst = vt + ((size_t)bh * HD + d0) * TT + t0;
#pragma unroll
    for (int i = 0; i < 32; i += 8)
        dst[(size_t)(ty + i) * TT + tx] = tsh[tx][ty + i];
}

// ---------------- LayerNorm ----------------
__global__ __launch_bounds__(256) void ln_kernel(const float* __restrict__ x,
                                                 const float* __restrict__ gam,
                                                 const float* __restrict__ bet,
                                                 float* __restrict__ out)
{
    int row = blockIdx.x;
    int t = threadIdx.x;
    const float* xr = x + (size_t)row * DD;
    float4 xv = *(const float4*)(xr + t * 4);
    float s = xv.x + xv.y + xv.z + xv.w;
    __shared__ float red[8];
#pragma unroll
    for (int o = 16; o; o >>= 1) s += __shfl_xor_sync(0xffffffffu, s, o);
    if ((t & 31) == 0) red[t >> 5] = s;
    __syncthreads();
    float mu = 0.f;
#pragma unroll
    for (int i = 0; i < 8; i++) mu += red[i];
    mu *= (1.0f / (float)DD);
    __syncthreads();
    float dx = xv.x - mu, dy = xv.y - mu, dz = xv.z - mu, dw = xv.w - mu;
    float s2 = dx * dx + dy * dy + dz * dz + dw * dw;
#pragma unroll
    for (int o = 16; o; o >>= 1) s2 += __shfl_xor_sync(0xffffffffu, s2, o);
    if ((t & 31) == 0) red[t >> 5] = s2;
    __syncthreads();
    float var = 0.f;
#pragma unroll
    for (int i = 0; i < 8; i++) var += red[i];
    var *= (1.0f / (float)DD);
    float inv = rsqrtf(var + LN_EPS);
    float4 gv = *(const float4*)(gam + t * 4);
    float4 bv = *(const float4*)(bet + t * 4);
    float4 o4;
    o4.x = dx * inv * gv.x + bv.x;
    o4.y = dy * inv * gv.y + bv.y;
    o4.z = dz * inv * gv.z + bv.z;
    o4.w = dw * inv * gv.w + bv.w;
    *(float4*)(out + (size_t)row * DD + t * 4) = o4;
}

// ---------------- tf32 mma.sync GEMM (as R7) ----------------
#define GSTAGE 32768
#define GSMEM  (3 * GSTAGE)

template<int EPI>
__global__ __launch_bounds__(128, 2) void mma_gemm(
    const float* __restrict__ A, const float* __restrict__ Bt,
    const float* __restrict__ bias, const float* __restrict__ resid,
    float* __restrict__ C, int M, int N, int K)
{
    extern __shared__ unsigned char smem_raw[];
    const uint32_t sbase = (uint32_t)__cvta_generic_to_shared(smem_raw);
    const int tid = threadIdx.x;
    const int wid = tid >> 5, lane = tid & 31;
    const int wm = wid & 1, wn = wid >> 1;
    const int g = lane >> 2, t = lane & 3;
    const int mb = blockIdx.y, nb = blockIdx.x;

    const int rl = tid >> 3;
    const int ch = tid & 7;
    const uint32_t sw16 = (uint32_t)((ch ^ (rl & 7)) * 16);
    const float* Ag = A + (size_t)(mb * 128 + rl) * K + ch * 4;
    const float* Bg = Bt + (size_t)(nb * 128 + rl) * K + ch * 4;

    const int l7 = lane & 7, mat = lane >> 3;
    const uint32_t a_rp = (uint32_t)((l7 + (mat & 1) * 8) * 128);
    const int a_ca = mat >> 1;
    const uint32_t b_rp = (uint32_t)((l7 + (mat >> 1) * 8) * 128);
    const int b_ca = mat & 1;

    float acc[4][8][4];
#pragma unroll
    for (int i = 0; i < 4; i++)
#pragma unroll
        for (int j = 0; j < 8; j++)
#pragma unroll
            for (int r = 0; r < 4; r++) acc[i][j][r] = 0.f;

    const int NC = K / 32;

    auto issue = [&](int cc, int s) {
        const uint32_t ab = sbase + (uint32_t)s * GSTAGE;
        const size_t ko = (size_t)cc * 32;
#pragma unroll
        for (int p = 0; p < 8; p++) {
            uint32_t soff = (uint32_t)((p * 16 + rl) * 128) + sw16;
            cp_async16(ab + soff,          Ag + (size_t)(p * 16) * K + ko);
            cp_async16(ab + 16384u + soff, Bg + (size_t)(p * 16) * K + ko);
        }
        CP_COMMIT();
    };

    issue(0, 0);
    issue(1, 1);

    for (int c = 0; c < NC; c++) {
        if (c < NC - 1) { CP_WAIT1(); } else { CP_WAIT0(); }
        __syncthreads();
        if (c + 2 < NC) issue(c + 2, (c + 2) % 3);

        const uint32_t sa = sbase + (uint32_t)(c % 3) * GSTAGE;
        const uint32_t sb = sa + 16384u;
#pragma unroll
        for (int ks = 0; ks < 4; ks++) {
            const int c0 = ks * 2;
            uint32_t af[4][4];
#pragma unroll
            for (int mt = 0; mt < 4; mt++) {
                uint32_t addr = sa + (uint32_t)((wm * 64 + mt * 16) * 128) + a_rp
                              + (uint32_t)(((c0 + a_ca) ^ l7) * 16);
                ldsm_x4(af[mt][0], af[mt][1], af[mt][2], af[mt][3], addr);
            }
            uint32_t bf[8][2];
#pragma unroll
            for (int pr = 0; pr < 4; pr++) {
                uint32_t addr = sb + (uint32_t)((wn * 64 + pr * 16) * 128) + b_rp
                              + (uint32_t)(((c0 + b_ca) ^ l7) * 16);
                ldsm_x4(bf[2 * pr][0], bf[2 * pr][1], bf[2 * pr + 1][0], bf[2 * pr + 1][1], addr);
            }
#pragma unroll
            for (int mt = 0; mt < 4; mt++)
#pragma unroll
                for (int nt = 0; nt < 8; nt++)
                    mma_tf32(acc[mt][nt], af[mt][0], af[mt][1], af[mt][2], af[mt][3],
                             bf[nt][0], bf[nt][1]);
        }
    }

#pragma unroll
    for (int mt = 0; mt < 4; mt++) {
        int row0 = mb * 128 + wm * 64 + mt * 16 + g;
#pragma unroll
        for (int nt = 0; nt < 8; nt++) {
            int col = nb * 128 + wn * 64 + nt * 8 + 2 * t;
#pragma unroll
            for (int half = 0; half < 2; half++) {
                int row = row0 + half * 8;
                float v0 = acc[mt][nt][half * 2 + 0];
                float v1 = acc[mt][nt][half * 2 + 1];
                if (EPI >= 1) { v0 += bias[col]; v1 += bias[col + 1]; }
                if (EPI == 3) { v0 = gelu_exact(v0); v1 = gelu_exact(v1); }
                if (EPI == 2) {
                    const float* rp = resid + (size_t)row * N + col;
                    v0 += rp[0]; v1 += rp[1];
                }
                float2 o2; o2.x = v0; o2.y = v1;
                *(float2*)(C + (size_t)row * N + col) = o2;
            }
        }
    }
}

// ---------------- tensor-core flash attention with BigBird bitmask ----------------
// 128 threads (4 warps); q-tile 64 (warp: 16 rows), k-tiles 64, d=64.
// Smem: Q 16K | K dbl 32K | Vt dbl 32K | P 16K = 96KB.
#define AQ_OFF 0
#define AK_OFF 16384
#define AV_OFF 49152
#define AP_OFF 81920
#define ATTN_SMEM 98304

__global__ __launch_bounds__(128, 2) void attn_kernel(
    const float* __restrict__ Q, const float* __restrict__ K,
    const float* __restrict__ Vt, const unsigned long long* __restrict__ mbits,
    float* __restrict__ O)
{
    extern __shared__ unsigned char sm_raw[];
    const uint32_t sb = (uint32_t)__cvta_generic_to_shared(sm_raw);
    const int tid = threadIdx.x;
    const int wid = tid >> 5, lane = tid & 31;
    const int l7 = lane & 7, mat = lane >> 3;
    const int g = lane >> 2, t = lane & 3;
    const int qb = blockIdx.x, h = blockIdx.y, b = blockIdx.z;
    const int q0 = qb * 64;

    const float* qg = Q + (size_t)b * TT * DD + (size_t)h * HD;
    const float* kg = K + (size_t)b * TT * DD + (size_t)h * HD;
    const float* vtg = Vt + (size_t)(b * HH + h) * HD * TT;

    // cp.async mapping: row = tid>>1 (0..63), chunks (tid&1)*8 + i
    const int crow = tid >> 1, chalf = (tid & 1) * 8;
    const uint32_t crsw = (uint32_t)(crow & 7);

    // tile loaders (16 chunks/row of 4 floats; two 8KB panels)
    auto ld_qk = [&](uint32_t dst, const float* gbase, int tok0) {
#pragma unroll
        for (int i = 0; i < 8; i++) {
            int cc = chalf + i;
            uint32_t sa = dst + (uint32_t)((cc >> 3) * 8192 + crow * 128)
                        + (uint32_t)((((uint32_t)(cc & 7)) ^ crsw) * 16);
            cp_async16(sa, gbase + (size_t)(tok0 + crow) * DD + cc * 4);
        }
    };
    auto ld_vt = [&](uint32_t dst, int k0) {
#pragma unroll
        for (int i = 0; i < 8; i++) {
            int cc = chalf + i;
            uint32_t sa = dst + (uint32_t)((cc >> 3) * 8192 + crow * 128)
                        + (uint32_t)((((uint32_t)(cc & 7)) ^ crsw) * 16);
            cp_async16(sa, vtg + (size_t)crow * TT + k0 + cc * 4);
        }
    };

    ld_qk(sb + AQ_OFF, qg, q0);
    ld_qk(sb + AK_OFF, kg, 0);
    ld_vt(sb + AV_OFF, 0);
    CP_COMMIT();

    float m0 = -INFINITY, m1 = -INFINITY, le0 = 0.f, le1 = 0.f;
    float oacc[8][4];
#pragma unroll
    for (int j = 0; j < 8; j++)
#pragma unroll
        for (int r = 0; r < 4; r++) oacc[j][r] = 0.f;

    const uint32_t a_rp = (uint32_t)((wid * 16 + l7 + (mat & 1) * 8) * 128);
    const int a_ca = mat >> 1;
    const uint32_t b_rp = (uint32_t)((l7 + (mat >> 1) * 8) * 128);
    const int b_ca = mat & 1;
    const int rowq0 = q0 + wid * 16 + g;

    for (int kb = 0; kb <= qb; kb++) {
        CP_WAIT0();
        __syncthreads();
        const int s = kb & 1;
        if (kb < qb) {
            ld_qk(sb + AK_OFF + (s ^ 1) * 16384, kg, (kb + 1) * 64);
            ld_vt(sb + AV_OFF + (s ^ 1) * 16384, (kb + 1) * 64);
            CP_COMMIT();
        }
        const uint32_t ksm = sb + AK_OFF + s * 16384;
        const uint32_t vsm = sb + AV_OFF + s * 16384;

        // ---- S = Q K^T (warp: m16 x n64, k=64) ----
        float sacc[8][4];
#pragma unroll
        for (int j = 0; j < 8; j++)
#pragma unroll
            for (int r = 0; r < 4; r++) sacc[j][r] = 0.f;
#pragma unroll
        for (int ks = 0; ks < 8; ks++) {
            const int c0 = ks * 2;
            uint32_t a0, a1, a2, a3;
            {
                int cc = c0 + a_ca;
                uint32_t addr = sb + AQ_OFF + (uint32_t)((cc >> 3) * 8192) + a_rp
                              + (uint32_t)((((uint32_t)(cc & 7)) ^ (uint32_t)l7) * 16);
                ldsm_x4(a0, a1, a2, a3, addr);
            }
            uint32_t bf[8][2];
#pragma unroll
            for (int pr = 0; pr < 4; pr++) {
                int cc = c0 + b_ca;
                uint32_t addr = ksm + (uint32_t)((cc >> 3) * 8192) + (uint32_t)(pr * 16 * 128)
                              + b_rp + (uint32_t)((((uint32_t)(cc & 7)) ^ (uint32_t)l7) * 16);
                ldsm_x4(bf[2 * pr][0], bf[2 * pr][1], bf[2 * pr + 1][0], bf[2 * pr + 1][1], addr);
            }
#pragma unroll
            for (int nt = 0; nt < 8; nt++)
                mma_tf32(sacc[nt], a0, a1, a2, a3, bf[nt][0], bf[nt][1]);
        }

        // ---- mask + scale + online softmax ----
        unsigned long long w0 = mbits[(size_t)rowq0 * 32 + kb];
        unsigned long long w1 = mbits[(size_t)(rowq0 + 8) * 32 + kb];
        float tm0 = -INFINITY, tm1 = -INFINITY;
#pragma unroll
        for (int nt = 0; nt < 8; nt++) {
            int col = nt * 8 + 2 * t;
            sacc[nt][0] = ((w0 >> col) & 1ull) ? sacc[nt][0] * 0.125f : -1e9f;
            sacc[nt][1] = ((w0 >> (col + 1)) & 1ull) ? sacc[nt][1] * 0.125f : -1e9f;
            sacc[nt][2] = ((w1 >> col) & 1ull) ? sacc[nt][2] * 0.125f : -1e9f;
            sacc[nt][3] = ((w1 >> (col + 1)) & 1ull) ? sacc[nt][3] * 0.125f : -1e9f;
            tm0 = fmaxf(tm0, fmaxf(sacc[nt][0], sacc[nt][1]));
            tm1 = fmaxf(tm1, fmaxf(sacc[nt][2], sacc[nt][3]));
        }
#pragma unroll
        for (int o = 1; o <= 2; o <<= 1) {
            tm0 = fmaxf(tm0, __shfl_xor_sync(0xffffffffu, tm0, o));
            tm1 = fmaxf(tm1, __shfl_xor_sync(0xffffffffu, tm1, o));
        }
        float mn0 = fmaxf(m0, tm0), mn1 = fmaxf(m1, tm1);
        float al0 = __expf(m0 - mn0), al1 = __expf(m1 - mn1);
        m0 = mn0; m1 = mn1;
        float rs0 = 0.f, rs1 = 0.f;
#pragma unroll
        for (int nt = 0; nt < 8; nt++) {
            float p0 = __expf(sacc[nt][0] - mn0);
            float p1 = __expf(sacc[nt][1] - mn0);
            float p2 = __expf(sacc[nt][2] - mn1);
            float p3 = __expf(sacc[nt][3] - mn1);
            rs0 += p0 + p1; rs1 += p2 + p3;
            // store P to smem (swizzled, ldmatrix-compatible)
            int cp = nt * 8 + 2 * t;
            int cc = cp >> 2;
            uint32_t base = sb + AP_OFF + (uint32_t)((cc >> 3) * 8192)
                          + (uint32_t)((((uint32_t)(cc & 7)) ^ (uint32_t)g) * 16)
                          + (uint32_t)((cp & 3) * 4);
            sts64(base + (uint32_t)((wid * 16 + g) * 128), p0, p1);
            sts64(base + (uint32_t)((wid * 16 + g + 8) * 128), p2, p3);
        }
#pragma unroll
        for (int o = 1; o <= 2; o <<= 1) {
            rs0 += __shfl_xor_sync(0xffffffffu, rs0, o);
            rs1 += __shfl_xor_sync(0xffffffffu, rs1, o);
        }
        le0 = le0 * al0 + rs0;
        le1 = le1 * al1 + rs1;
#pragma unroll
        for (int nt = 0; nt < 8; nt++) {
            oacc[nt][0] *= al0; oacc[nt][1] *= al0;
            oacc[nt][2] *= al1; oacc[nt][3] *= al1;
        }
        __syncthreads();   // P visible to whole warp's ldmatrix (and block-wide safety)

        // ---- O += P V (warp: m16 x n64(d), k=64(tokens)) ----
#pragma unroll
        for (int ks = 0; ks < 8; ks++) {
            const int c0 = ks * 2;
            uint32_t a0, a1, a2, a3;
            {
                int cc = c0 + a_ca;
                uint32_t addr = sb + AP_OFF + (uint32_t)((cc >> 3) * 8192) + a_rp
                              + (uint32_t)((((uint32_t)(cc & 7)) ^ (uint32_t)l7) * 16);
                ldsm_x4(a0, a1, a2, a3, addr);
            }
            uint32_t bf[8][2];
#pragma unroll
            for (int pr = 0; pr < 4; pr++) {
                int cc = c0 + b_ca;
                uint32_t addr = vsm + (uint32_t)((cc >> 3) * 8192) + (uint32_t)(pr * 16 * 128)
                              + b_rp + (uint32_t)((((uint32_t)(cc & 7)) ^ (uint32_t)l7) * 16);
                ldsm_x4(bf[2 * pr][0], bf[2 * pr][1], bf[2 * pr + 1][0], bf[2 * pr + 1][1], addr);
            }
#pragma unroll
            for (int nt = 0; nt < 8; nt++)
                mma_tf32(oacc[nt], a0, a1, a2, a3, bf[nt][0], bf[nt][1]);
        }
    }

    // ---- normalize + write ----
    float inv0 = 1.0f / le0, inv1 = 1.0f / le1;
    float* ob = O + (size_t)b * TT * DD + (size_t)h * HD;
#pragma unroll
    for (int nt = 0; nt < 8; nt++) {
        int col = nt * 8 + 2 * t;
        float2 o2;
        o2.x = oacc[nt][0] * inv0; o2.y = oacc[nt][1] * inv0;
        *(float2*)(ob + (size_t)rowq0 * DD + col) = o2;
        o2.x = oacc[nt][2] * inv1; o2.y = oacc[nt][3] * inv1;
        *(float2*)(ob + (size_t)(rowq0 + 8) * DD + col) = o2;
    }
}

// ---------------- launch ----------------
extern "C" void kernel_launch(void* const* d_in, const int* in_sizes, int n_in,
                              void* d_out, int out_size)
{
    (void)in_sizes; (void)n_in; (void)out_size;
    const float* x     = (const float*)d_in[0];
    const unsigned char* mask_raw = (const unsigned char*)d_in[1];
    const float* ln1_g = (const float*)d_in[2];
    const float* ln1_b = (const float*)d_in[3];
    const float* ln2_g = (const float*)d_in[4];
    const float* ln2_b = (const float*)d_in[5];
    const float* Wq    = (const float*)d_in[6];
    const float* Wk    = (const float*)d_in[7];
    const float* Wv    = (const float*)d_in[8];
    const float* Wo    = (const float*)d_in[9];
    const float* bo    = (const float*)d_in[10];
    const float* W1    = (const float*)d_in[11];
    const float* b1    = (const float*)d_in[12];
    const float* W2    = (const float*)d_in[13];
    const float* b2    = (const float*)d_in[14];
    float* out = (float*)d_out;

    float *h, *q, *k, *v, *vt, *attn, *xmid, *h2, *ff;
    float *wqt, *wkt, *wvt, *wot, *w1t, *w2t;
    unsigned long long* mbits;
    cudaGetSymbolAddress((void**)&h,    g_h);
    cudaGetSymbolAddress((void**)&q,    g_q);
    cudaGetSymbolAddress((void**)&k,    g_k);
    cudaGetSymbolAddress((void**)&v,    g_v);
    cudaGetSymbolAddress((void**)&vt,   g_vt);
    cudaGetSymbolAddress((void**)&attn, g_attn);
    cudaGetSymbolAddress((void**)&xmid, g_xmid);
    cudaGetSymbolAddress((void**)&h2,   g_h2);
    cudaGetSymbolAddress((void**)&ff,   g_ff);
    cudaGetSymbolAddress((void**)&wqt,  g_wqt);
    cudaGetSymbolAddress((void**)&wkt,  g_wkt);
    cudaGetSymbolAddress((void**)&wvt,  g_wvt);
    cudaGetSymbolAddress((void**)&wot,  g_wot);
    cudaGetSymbolAddress((void**)&w1t,  g_w1t);
    cudaGetSymbolAddress((void**)&w2t,  g_w2t);
    cudaGetSymbolAddress((void**)&mbits, g_mask_bits);

    cudaFuncSetAttribute(attn_kernel, cudaFuncAttributeMaxDynamicSharedMemorySize, ATTN_SMEM);
    cudaFuncSetAttribute(mma_gemm<0>, cudaFuncAttributeMaxDynamicSharedMemorySize, GSMEM);
    cudaFuncSetAttribute(mma_gemm<2>, cudaFuncAttributeMaxDynamicSharedMemorySize, GSMEM);
    cudaFuncSetAttribute(mma_gemm<3>, cudaFuncAttributeMaxDynamicSharedMemorySize, GSMEM);

    // 0) mask bits + weight transposes
    mask_bits_kernel<<<(TT * (TT / 64)) / 256, 256>>>(mask_raw);
    transpose_kernel<<<dim3(DD / 32, DD / 32), 256>>>(Wq, wqt, DD, DD);
    transpose_kernel<<<dim3(DD / 32, DD / 32), 256>>>(Wk, wkt, DD, DD);
    transpose_kernel<<<dim3(DD / 32, DD / 32), 256>>>(Wv, wvt, DD, DD);
    transpose_kernel<<<dim3(DD / 32, DD / 32), 256>>>(Wo, wot, DD, DD);
    transpose_kernel<<<dim3(FF / 32, DD / 32), 256>>>(W1, w1t, DD, FF);
    transpose_kernel<<<dim3(DD / 32, FF / 32), 256>>>(W2, w2t, FF, DD);
    // 1) LN1
    ln_kernel<<<ROWS, 256>>>(x, ln1_g, ln1_b, h);
    // 2) Q,K,V projections
    dim3 g1024(DD / 128, ROWS / 128);
    mma_gemm<0><<<g1024, 128, GSMEM>>>(h, wqt, nullptr, nullptr, q, ROWS, DD, DD);
    mma_gemm<0><<<g1024, 128, GSMEM>>>(h, wkt, nullptr, nullptr, k, ROWS, DD, DD);
    mma_gemm<0><<<g1024, 128, GSMEM>>>(h, wvt, nullptr, nullptr, v, ROWS, DD, DD);
    // 2b) V transpose per head
    vtrans_kernel<<<dim3(TT / 32, HD / 32, BB * HH), 256>>>(v, vt);
    // 3) attention (tensor core)
    attn_kernel<<<dim3(TT / 64, HH, BB), 128, ATTN_SMEM>>>(q, k, vt, mbits, attn);
    // 4) Wo + bias + residual(x)
    mma_gemm<2><<<g1024, 128, GSMEM>>>(attn, wot, bo, x, xmid, ROWS, DD, DD);
    // 5) LN2
    ln_kernel<<<ROWS, 256>>>(xmid, ln2_g, ln2_b, h2);
    // 6) FFN up + GELU
    mma_gemm<3><<<dim3(FF / 128, ROWS / 128), 128, GSMEM>>>(h2, w1t, b1, nullptr, ff, ROWS, FF, DD);
    // 7) FFN down + bias + residual(xmid) -> out
    mma_gemm<2><<<g1024, 128, GSMEM>>>(ff, w2t, b2, xmid, out, ROWS, DD, FF);
}

// round 10
// speedup vs baseline: 3.0877x; 1.0158x over previous
#include <cuda_runtime.h>
#include <math.h>
#include <stdint.h>

// ---------------- problem constants ----------------
#define BB 2
#define TT 2048
#define DD 1024
#define HH 16
#define HD 64
#define FF 4096
#define ROWS (BB * TT)          // 4096
#define LN_EPS 1e-5f
#define QKVN (3 * DD)           // 3072

// ---------------- scratch (__device__ globals; no allocation) ----------------
__device__ float g_h[ROWS * DD];
__device__ float g_qkv[ROWS * QKVN];        // fused Q|K|V, row stride 3072
__device__ float g_vt[BB * HH * HD * TT];   // [b,h][d][t]
__device__ float g_attn[ROWS * DD];
__device__ float g_xmid[ROWS * DD];
__device__ float g_h2[ROWS * DD];
__device__ float g_ff[ROWS * FF];
__device__ unsigned long long g_mask_bits[TT * (TT / 64)];
// transposed (n-major, k-contiguous) tf32-rounded weights
__device__ float g_wqkvt[QKVN * DD];        // rows 0..1023 Wq^T | 1024.. Wk^T | 2048.. Wv^T
__device__ float g_wot[DD * DD];
__device__ float g_w1t[FF * DD];
__device__ float g_w2t[DD * FF];

// ---------------- helpers ----------------
__device__ __forceinline__ uint32_t f2tf32(float f) {
    uint32_t r;
    asm("cvt.rna.tf32.f32 %0, %1;" : "=r"(r) : "f"(f));
    return r;
}
__device__ __forceinline__ float gelu_exact(float x) {
    return 0.5f * x * (1.0f + erff(x * 0.70710678118654752f));
}
__device__ __forceinline__ void mma_tf32(float c[4], uint32_t a0, uint32_t a1,
                                         uint32_t a2, uint32_t a3,
                                         uint32_t b0, uint32_t b1) {
    asm volatile(
        "mma.sync.aligned.m16n8k8.row.col.f32.tf32.tf32.f32 "
        "{%0,%1,%2,%3}, {%4,%5,%6,%7}, {%8,%9}, {%0,%1,%2,%3};"
        : "+f"(c[0]), "+f"(c[1]), "+f"(c[2]), "+f"(c[3])
        : "r"(a0), "r"(a1), "r"(a2), "r"(a3), "r"(b0), "r"(b1));
}
__device__ __forceinline__ void ldsm_x4(uint32_t& r0, uint32_t& r1,
                                        uint32_t& r2, uint32_t& r3, uint32_t addr) {
    asm volatile("ldmatrix.sync.aligned.m8n8.x4.shared.b16 {%0,%1,%2,%3}, [%4];"
                 : "=r"(r0), "=r"(r1), "=r"(r2), "=r"(r3) : "r"(addr));
}
__device__ __forceinline__ void cp_async16(uint32_t saddr, const float* gaddr) {
    asm volatile("cp.async.cg.shared.global [%0], [%1], 16;" :: "r"(saddr), "l"(gaddr));
}
#define CP_COMMIT() asm volatile("cp.async.commit_group;" ::: "memory")
#define CP_WAIT1() asm volatile("cp.async.wait_group 1;" ::: "memory")
#define CP_WAIT0() asm volatile("cp.async.wait_group 0;" ::: "memory")
__device__ __forceinline__ void sts64(uint32_t addr, float a, float b) {
    asm volatile("st.shared.v2.f32 [%0], {%1,%2};" :: "r"(addr), "f"(a), "f"(b));
}

// ---------------- mask repack: dtype-agnostic -> 64-bit rows ----------------
__global__ __launch_bounds__(256) void mask_bits_kernel(const unsigned char* __restrict__ raw)
{
    int i = blockIdx.x * 256 + threadIdx.x;    // word index < TT*32
    int row = i >> 5, w = i & 31;
    bool one_byte = (raw[2048] != 0);
    unsigned long long bits = 0ull;
    if (one_byte) {
        const unsigned char* p = raw + (size_t)row * TT + w * 64;
#pragma unroll 8
        for (int j = 0; j < 64; j++) if (p[j]) bits |= 1ull << j;
    } else {
        const unsigned int* p = (const unsigned int*)raw + (size_t)row * TT + w * 64;
#pragma unroll 8
        for (int j = 0; j < 64; j++) if (p[j]) bits |= 1ull << j;
    }
    g_mask_bits[i] = bits;
}

// ---------------- 4x DxD weight transpose (+rna tf32): z selects matrix ----------------
__global__ __launch_bounds__(256) void transpose4_kernel(
    const float* __restrict__ Wq, const float* __restrict__ Wk,
    const float* __restrict__ Wv, const float* __restrict__ Wo,
    float* __restrict__ wqkvt, float* __restrict__ wot)
{
    __shared__ float t[32][33];
    int z = blockIdx.z;
    const float* src = (z == 0) ? Wq : (z == 1) ? Wk : (z == 2) ? Wv : Wo;
    float* dst = (z < 3) ? (wqkvt + (size_t)z * DD * DD) : wot;
    int c0 = blockIdx.x * 32, r0 = blockIdx.y * 32;
    int tx = threadIdx.x & 31, ty = threadIdx.x >> 5;
#pragma unroll
    for (int i = 0; i < 32; i += 8)
        t[ty + i][tx] = src[(size_t)(r0 + ty + i) * DD + c0 + tx];
    __syncthreads();
#pragma unroll
    for (int i = 0; i < 32; i += 8)
        dst[(size_t)(c0 + ty + i) * DD + r0 + tx] = __uint_as_float(f2tf32(t[tx][ty + i]));
}

// ---------------- general weight transpose (+rna tf32) ----------------
__global__ __launch_bounds__(256) void transpose_kernel(const float* __restrict__ src,
                                                        float* __restrict__ dst,
                                                        int R, int C)
{
    __shared__ float t[32][33];
    int c0 = blockIdx.x * 32, r0 = blockIdx.y * 32;
    int tx = threadIdx.x & 31, ty = threadIdx.x >> 5;
#pragma unroll
    for (int i = 0; i < 32; i += 8)
        t[ty + i][tx] = src[(size_t)(r0 + ty + i) * C + c0 + tx];
    __syncthreads();
#pragma unroll
    for (int i = 0; i < 32; i += 8)
        dst[(size_t)(c0 + ty + i) * R + r0 + tx] = __uint_as_float(f2tf32(t[tx][ty + i]));
}

// ---------------- V transpose per head: vt[b,h][d][t] = qkv[b][t][2048 + h*64 + d] ----------------
__global__ __launch_bounds__(256) void vtrans_kernel(const float* __restrict__ qkv,
                                                     float* __restrict__ vt)
{
    __shared__ float tsh[32][33];
    int bh = blockIdx.z;
    int b = bh >> 4, h = bh & 15;
    int t0 = blockIdx.x * 32, d0 = blockIdx.y * 32;
    int tx = threadIdx.x & 31, ty = threadIdx.x >> 5;
    const float* src = qkv + (size_t)b * TT * QKVN + 2048 + (size_t)h * HD;
#pragma unroll
    for (int i = 0; i < 32; i += 8)
        tsh[ty + i][tx] = src[(size_t)(t0 + ty + i) * QKVN + d0 + tx];
    __syncthreads();
    float* dst = vt + ((size_t)bh * HD + d0) * TT + t0;
#pragma unroll
    for (int i = 0; i < 32; i += 8)
        dst[(size_t)(ty + i) * TT + tx] = tsh[tx][ty + i];
}

// ---------------- LayerNorm ----------------
__global__ __launch_bounds__(256) void ln_kernel(const float* __restrict__ x,
                                                 const float* __restrict__ gam,
                                                 const float* __restrict__ bet,
                                                 float* __restrict__ out)
{
    int row = blockIdx.x;
    int t = threadIdx.x;
    const float* xr = x + (size_t)row * DD;
    float4 xv = *(const float4*)(xr + t * 4);
    float s = xv.x + xv.y + xv.z + xv.w;
    __shared__ float red[8];
#pragma unroll
    for (int o = 16; o; o >>= 1) s += __shfl_xor_sync(0xffffffffu, s, o);
    if ((t & 31) == 0) red[t >> 5] = s;
    __syncthreads();
    float mu = 0.f;
#pragma unroll
    for (int i = 0; i < 8; i++) mu += red[i];
    mu *= (1.0f / (float)DD);
    __syncthreads();
    float dx = xv.x - mu, dy = xv.y - mu, dz = xv.z - mu, dw = xv.w - mu;
    float s2 = dx * dx + dy * dy + dz * dz + dw * dw;
#pragma unroll
    for (int o = 16; o; o >>= 1) s2 += __shfl_xor_sync(0xffffffffu, s2, o);
    if ((t & 31) == 0) red[t >> 5] = s2;
    __syncthreads();
    float var = 0.f;
#pragma unroll
    for (int i = 0; i < 8; i++) var += red[i];
    var *= (1.0f / (float)DD);
    float inv = rsqrtf(var + LN_EPS);
    float4 gv = *(const float4*)(gam + t * 4);
    float4 bv = *(const float4*)(bet + t * 4);
    float4 o4;
    o4.x = dx * inv * gv.x + bv.x;
    o4.y = dy * inv * gv.y + bv.y;
    o4.z = dz * inv * gv.z + bv.z;
    o4.w = dw * inv * gv.w + bv.w;
    *(float4*)(out + (size_t)row * DD + t * 4) = o4;
}

// ---------------- tf32 mma.sync GEMM with fragment double-buffering ----------------
#define GSTAGE 32768
#define GSMEM  (3 * GSTAGE)

template<int EPI>
__global__ __launch_bounds__(128, 2) void mma_gemm(
    const float* __restrict__ A, const float* __restrict__ Bt,
    const float* __restrict__ bias, const float* __restrict__ resid,
    float* __restrict__ C, int M, int N, int K)
{
    extern __shared__ unsigned char smem_raw[];
    const uint32_t sbase = (uint32_t)__cvta_generic_to_shared(smem_raw);
    const int tid = threadIdx.x;
    const int wid = tid >> 5, lane = tid & 31;
    const int wm = wid & 1, wn = wid >> 1;
    const int g = lane >> 2, t = lane & 3;
    const int mb = blockIdx.y, nb = blockIdx.x;

    const int rl = tid >> 3;
    const int ch = tid & 7;
    const uint32_t sw16 = (uint32_t)((ch ^ (rl & 7)) * 16);
    const float* Ag = A + (size_t)(mb * 128 + rl) * K + ch * 4;
    const float* Bg = Bt + (size_t)(nb * 128 + rl) * K + ch * 4;

    const int l7 = lane & 7, mat = lane >> 3;
    const uint32_t a_rp = (uint32_t)((l7 + (mat & 1) * 8) * 128);
    const int a_ca = mat >> 1;
    const uint32_t b_rp = (uint32_t)((l7 + (mat >> 1) * 8) * 128);
    const int b_ca = mat & 1;

    float acc[4][8][4];
#pragma unroll
    for (int i = 0; i < 4; i++)
#pragma unroll
        for (int j = 0; j < 8; j++)
#pragma unroll
            for (int r = 0; r < 4; r++) acc[i][j][r] = 0.f;

    const int NC = K / 32;

    auto issue = [&](int cc, int s) {
        const uint32_t ab = sbase + (uint32_t)s * GSTAGE;
        const size_t ko = (size_t)cc * 32;
#pragma unroll
        for (int p = 0; p < 8; p++) {
            uint32_t soff = (uint32_t)((p * 16 + rl) * 128) + sw16;
            cp_async16(ab + soff,          Ag + (size_t)(p * 16) * K + ko);
            cp_async16(ab + 16384u + soff, Bg + (size_t)(p * 16) * K + ko);
        }
        CP_COMMIT();
    };

    issue(0, 0);
    issue(1, 1);

    uint32_t af[2][4][4], bf[2][8][2];

    for (int c = 0; c < NC; c++) {
        if (c < NC - 1) { CP_WAIT1(); } else { CP_WAIT0(); }
        __syncthreads();
        if (c + 2 < NC) issue(c + 2, (c + 2) % 3);

        const uint32_t sa = sbase + (uint32_t)(c % 3) * GSTAGE;
        const uint32_t sb = sa + 16384u;

        auto load_frags = [&](int ks, uint32_t (*afd)[4], uint32_t (*bfd)[2]) {
            const int c0 = ks * 2;
#pragma unroll
            for (int mt = 0; mt < 4; mt++) {
                uint32_t addr = sa + (uint32_t)((wm * 64 + mt * 16) * 128) + a_rp
                              + (uint32_t)(((c0 + a_ca) ^ l7) * 16);
                ldsm_x4(afd[mt][0], afd[mt][1], afd[mt][2], afd[mt][3], addr);
            }
#pragma unroll
            for (int pr = 0; pr < 4; pr++) {
                uint32_t addr = sb + (uint32_t)((wn * 64 + pr * 16) * 128) + b_rp
                              + (uint32_t)(((c0 + b_ca) ^ l7) * 16);
                ldsm_x4(bfd[2 * pr][0], bfd[2 * pr][1], bfd[2 * pr + 1][0], bfd[2 * pr + 1][1], addr);
            }
        };

        load_frags(0, af[0], bf[0]);
#pragma unroll
        for (int ks = 0; ks < 4; ks++) {
            const int cur = ks & 1;
            if (ks < 3) load_frags(ks + 1, af[cur ^ 1], bf[cur ^ 1]);
#pragma unroll
            for (int mt = 0; mt < 4; mt++)
#pragma unroll
                for (int nt = 0; nt < 8; nt++)
                    mma_tf32(acc[mt][nt], af[cur][mt][0], af[cur][mt][1],
                             af[cur][mt][2], af[cur][mt][3],
                             bf[cur][nt][0], bf[cur][nt][1]);
        }
    }

#pragma unroll
    for (int mt = 0; mt < 4; mt++) {
        int row0 = mb * 128 + wm * 64 + mt * 16 + g;
#pragma unroll
        for (int nt = 0; nt < 8; nt++) {
            int col = nb * 128 + wn * 64 + nt * 8 + 2 * t;
#pragma unroll
            for (int half = 0; half < 2; half++) {
                int row = row0 + half * 8;
                float v0 = acc[mt][nt][half * 2 + 0];
                float v1 = acc[mt][nt][half * 2 + 1];
                if (EPI >= 1) { v0 += bias[col]; v1 += bias[col + 1]; }
                if (EPI == 3) { v0 = gelu_exact(v0); v1 = gelu_exact(v1); }
                if (EPI == 2) {
                    const float* rp = resid + (size_t)row * N + col;
                    v0 += rp[0]; v1 += rp[1];
                }
                float2 o2; o2.x = v0; o2.y = v1;
                *(float2*)(C + (size_t)row * N + col) = o2;
            }
        }
    }
}

// ---------------- tensor-core flash attention with BigBird bitmask ----------------
#define AQ_OFF 0
#define AK_OFF 16384
#define AV_OFF 49152
#define AP_OFF 81920
#define ATTN_SMEM 98304

__global__ __launch_bounds__(128, 2) void attn_kernel(
    const float* __restrict__ QKV, const float* __restrict__ Vt,
    const unsigned long long* __restrict__ mbits, float* __restrict__ O)
{
    extern __shared__ unsigned char sm_raw[];
    const uint32_t sb = (uint32_t)__cvta_generic_to_shared(sm_raw);
    const int tid = threadIdx.x;
    const int wid = tid >> 5, lane = tid & 31;
    const int l7 = lane & 7, mat = lane >> 3;
    const int g = lane >> 2, t = lane & 3;
    const int qb = blockIdx.x, h = blockIdx.y, b = blockIdx.z;
    const int q0 = qb * 64;

    const float* qg = QKV + (size_t)b * TT * QKVN + (size_t)h * HD;          // Q cols
    const float* kg = QKV + (size_t)b * TT * QKVN + 1024 + (size_t)h * HD;   // K cols
    const float* vtg = Vt + (size_t)(b * HH + h) * HD * TT;

    const int crow = tid >> 1, chalf = (tid & 1) * 8;
    const uint32_t crsw = (uint32_t)(crow & 7);

    auto ld_qk = [&](uint32_t dst, const float* gbase, int tok0) {
#pragma unroll
        for (int i = 0; i < 8; i++) {
            int cc = chalf + i;
            uint32_t sa = dst + (uint32_t)((cc >> 3) * 8192 + crow * 128)
                        + (uint32_t)((((uint32_t)(cc & 7)) ^ crsw) * 16);
            cp_async16(sa, gbase + (size_t)(tok0 + crow) * QKVN + cc * 4);
        }
    };
    auto ld_vt = [&](uint32_t dst, int k0) {
#pragma unroll
        for (int i = 0; i < 8; i++) {
            int cc = chalf + i;
            uint32_t sa = dst + (uint32_t)((cc >> 3) * 8192 + crow * 128)
                        + (uint32_t)((((uint32_t)(cc & 7)) ^ crsw) * 16);
            cp_async16(sa, vtg + (size_t)crow * TT + k0 + cc * 4);
        }
    };

    ld_qk(sb + AQ_OFF, qg, q0);
    ld_qk(sb + AK_OFF, kg, 0);
    ld_vt(sb + AV_OFF, 0);
    CP_COMMIT();

    float m0 = -INFINITY, m1 = -INFINITY, le0 = 0.f, le1 = 0.f;
    float oacc[8][4];
#pragma unroll
    for (int j = 0; j < 8; j++)
#pragma unroll
        for (int r = 0; r < 4; r++) oacc[j][r] = 0.f;

    const uint32_t a_rp = (uint32_t)((wid * 16 + l7 + (mat & 1) * 8) * 128);
    const int a_ca = mat >> 1;
    const uint32_t b_rp = (uint32_t)((l7 + (mat >> 1) * 8) * 128);
    const int b_ca = mat & 1;
    const int rowq0 = q0 + wid * 16 + g;

    for (int kb = 0; kb <= qb; kb++) {
        CP_WAIT0();
        __syncthreads();
        const int s = kb & 1;
        if (kb < qb) {
            ld_qk(sb + AK_OFF + (s ^ 1) * 16384, kg, (kb + 1) * 64);
            ld_vt(sb + AV_OFF + (s ^ 1) * 16384, (kb + 1) * 64);
            CP_COMMIT();
        }
        const uint32_t ksm = sb + AK_OFF + s * 16384;
        const uint32_t vsm = sb + AV_OFF + s * 16384;

        // ---- S = Q K^T ----
        float sacc[8][4];
#pragma unroll
        for (int j = 0; j < 8; j++)
#pragma unroll
            for (int r = 0; r < 4; r++) sacc[j][r] = 0.f;
#pragma unroll
        for (int ks = 0; ks < 8; ks++) {
            const int c0 = ks * 2;
            uint32_t a0, a1, a2, a3;
            {
                int cc = c0 + a_ca;
                uint32_t addr = sb + AQ_OFF + (uint32_t)((cc >> 3) * 8192) + a_rp
                              + (uint32_t)((((uint32_t)(cc & 7)) ^ (uint32_t)l7) * 16);
                ldsm_x4(a0, a1, a2, a3, addr);
            }
            uint32_t bf[8][2];
#pragma unroll
            for (int pr = 0; pr < 4; pr++) {
                int cc = c0 + b_ca;
                uint32_t addr = ksm + (uint32_t)((cc >> 3) * 8192) + (uint32_t)(pr * 16 * 128)
                              + b_rp + (uint32_t)((((uint32_t)(cc & 7)) ^ (uint32_t)l7) * 16);
                ldsm_x4(bf[2 * pr][0], bf[2 * pr][1], bf[2 * pr + 1][0], bf[2 * pr + 1][1], addr);
            }
#pragma unroll
            for (int nt = 0; nt < 8; nt++)
                mma_tf32(sacc[nt], a0, a1, a2, a3, bf[nt][0], bf[nt][1]);
        }

        // ---- mask + scale + online softmax ----
        unsigned long long w0 = mbits[(size_t)rowq0 * 32 + kb];
        unsigned long long w1 = mbits[(size_t)(rowq0 + 8) * 32 + kb];
        float tm0 = -INFINITY, tm1 = -INFINITY;
#pragma unroll
        for (int nt = 0; nt < 8; nt++) {
            int col = nt * 8 + 2 * t;
            sacc[nt][0] = ((w0 >> col) & 1ull) ? sacc[nt][0] * 0.125f : -1e9f;
            sacc[nt][1] = ((w0 >> (col + 1)) & 1ull) ? sacc[nt][1] * 0.125f : -1e9f;
            sacc[nt][2] = ((w1 >> col) & 1ull) ? sacc[nt][2] * 0.125f : -1e9f;
            sacc[nt][3] = ((w1 >> (col + 1)) & 1ull) ? sacc[nt][3] * 0.125f : -1e9f;
            tm0 = fmaxf(tm0, fmaxf(sacc[nt][0], sacc[nt][1]));
            tm1 = fmaxf(tm1, fmaxf(sacc[nt][2], sacc[nt][3]));
        }
#pragma unroll
        for (int o = 1; o <= 2; o <<= 1) {
            tm0 = fmaxf(tm0, __shfl_xor_sync(0xffffffffu, tm0, o));
            tm1 = fmaxf(tm1, __shfl_xor_sync(0xffffffffu, tm1, o));
        }
        float mn0 = fmaxf(m0, tm0), mn1 = fmaxf(m1, tm1);
        float al0 = __expf(m0 - mn0), al1 = __expf(m1 - mn1);
        m0 = mn0; m1 = mn1;
        float rs0 = 0.f, rs1 = 0.f;
#pragma unroll
        for (int nt = 0; nt < 8; nt++) {
            float p0 = __expf(sacc[nt][0] - mn0);
            float p1 = __expf(sacc[nt][1] - mn0);
            float p2 = __expf(sacc[nt][2] - mn1);
            float p3 = __expf(sacc[nt][3] - mn1);
            rs0 += p0 + p1; rs1 += p2 + p3;
            int cp = nt * 8 + 2 * t;
            int cc = cp >> 2;
            uint32_t base = sb + AP_OFF + (uint32_t)((cc >> 3) * 8192)
                          + (uint32_t)((((uint32_t)(cc & 7)) ^ (uint32_t)g) * 16)
                          + (uint32_t)((cp & 3) * 4);
            sts64(base + (uint32_t)((wid * 16 + g) * 128), p0, p1);
            sts64(base + (uint32_t)((wid * 16 + g + 8) * 128), p2, p3);
        }
#pragma unroll
        for (int o = 1; o <= 2; o <<= 1) {
            rs0 += __shfl_xor_sync(0xffffffffu, rs0, o);
            rs1 += __shfl_xor_sync(0xffffffffu, rs1, o);
        }
        le0 = le0 * al0 + rs0;
        le1 = le1 * al1 + rs1;
#pragma unroll
        for (int nt = 0; nt < 8; nt++) {
            oacc[nt][0] *= al0; oacc[nt][1] *= al0;
            oacc[nt][2] *= al1; oacc[nt][3] *= al1;
        }
        __syncwarp(0xffffffffu);   // P is warp-local: stores visible to warp's ldmatrix

        // ---- O += P V ----
#pragma unroll
        for (int ks = 0; ks < 8; ks++) {
            const int c0 = ks * 2;
            uint32_t a0, a1, a2, a3;
            {
                int cc = c0 + a_ca;
                uint32_t addr = sb + AP_OFF + (uint32_t)((cc >> 3) * 8192) + a_rp
                              + (uint32_t)((((uint32_t)(cc & 7)) ^ (uint32_t)l7) * 16);
                ldsm_x4(a0, a1, a2, a3, addr);
            }
            uint32_t bf[8][2];
#pragma unroll
            for (int pr = 0; pr < 4; pr++) {
                int cc = c0 + b_ca;
                uint32_t addr = vsm + (uint32_t)((cc >> 3) * 8192) + (uint32_t)(pr * 16 * 128)
                              + b_rp + (uint32_t)((((uint32_t)(cc & 7)) ^ (uint32_t)l7) * 16);
                ldsm_x4(bf[2 * pr][0], bf[2 * pr][1], bf[2 * pr + 1][0], bf[2 * pr + 1][1], addr);
            }
#pragma unroll
            for (int nt = 0; nt < 8; nt++)
                mma_tf32(oacc[nt], a0, a1, a2, a3, bf[nt][0], bf[nt][1]);
        }
    }

    // ---- normalize + write ----
    float inv0 = 1.0f / le0, inv1 = 1.0f / le1;
    float* ob = O + (size_t)b * TT * DD + (size_t)h * HD;
#pragma unroll
    for (int nt = 0; nt < 8; nt++) {
        int col = nt * 8 + 2 * t;
        float2 o2;
        o2.x = oacc[nt][0] * inv0; o2.y = oacc[nt][1] * inv0;
        *(float2*)(ob + (size_t)rowq0 * DD + col) = o2;
        o2.x = oacc[nt][2] * inv1; o2.y = oacc[nt][3] * inv1;
        *(float2*)(ob + (size_t)(rowq0 + 8) * DD + col) = o2;
    }
}

// ---------------- launch ----------------
extern "C" void kernel_launch(void* const* d_in, const int* in_sizes, int n_in,
                              void* d_out, int out_size)
{
    (void)in_sizes; (void)n_in; (void)out_size;
    const float* x     = (const float*)d_in[0];
    const unsigned char* mask_raw = (const unsigned char*)d_in[1];
    const float* ln1_g = (const float*)d_in[2];
    const float* ln1_b = (const float*)d_in[3];
    const float* ln2_g = (const float*)d_in[4];
    const float* ln2_b = (const float*)d_in[5];
    const float* Wq    = (const float*)d_in[6];
    const float* Wk    = (const float*)d_in[7];
    const float* Wv    = (const float*)d_in[8];
    const float* Wo    = (const float*)d_in[9];
    const float* bo    = (const float*)d_in[10];
    const float* W1    = (const float*)d_in[11];
    const float* b1    = (const float*)d_in[12];
    const float* W2    = (const float*)d_in[13];
    const float* b2    = (const float*)d_in[14];
    float* out = (float*)d_out;

    float *h, *qkv, *vt, *attn, *xmid, *h2, *ff;
    float *wqkvt, *wot, *w1t, *w2t;
    unsigned long long* mbits;
    cudaGetSymbolAddress((void**)&h,     g_h);
    cudaGetSymbolAddress((void**)&qkv,   g_qkv);
    cudaGetSymbolAddress((void**)&vt,    g_vt);
    cudaGetSymbolAddress((void**)&attn,  g_attn);
    cudaGetSymbolAddress((void**)&xmid,  g_xmid);
    cudaGetSymbolAddress((void**)&h2,    g_h2);
    cudaGetSymbolAddress((void**)&ff,    g_ff);
    cudaGetSymbolAddress((void**)&wqkvt, g_wqkvt);
    cudaGetSymbolAddress((void**)&wot,   g_wot);
    cudaGetSymbolAddress((void**)&w1t,   g_w1t);
    cudaGetSymbolAddress((void**)&w2t,   g_w2t);
    cudaGetSymbolAddress((void**)&mbits, g_mask_bits);

    cudaFuncSetAttribute(attn_kernel, cudaFuncAttributeMaxDynamicSharedMemorySize, ATTN_SMEM);
    cudaFuncSetAttribute(mma_gemm<0>, cudaFuncAttributeMaxDynamicSharedMemorySize, GSMEM);
    cudaFuncSetAttribute(mma_gemm<2>, cudaFuncAttributeMaxDynamicSharedMemorySize, GSMEM);
    cudaFuncSetAttribute(mma_gemm<3>, cudaFuncAttributeMaxDynamicSharedMemorySize, GSMEM);

    // 0) mask bits + weight transposes
    mask_bits_kernel<<<(TT * (TT / 64)) / 256, 256>>>(mask_raw);
    transpose4_kernel<<<dim3(DD / 32, DD / 32, 4), 256>>>(Wq, Wk, Wv, Wo, wqkvt, wot);
    transpose_kernel<<<dim3(FF / 32, DD / 32), 256>>>(W1, w1t, DD, FF);
    transpose_kernel<<<dim3(DD / 32, FF / 32), 256>>>(W2, w2t, FF, DD);
    // 1) LN1
    ln_kernel<<<ROWS, 256>>>(x, ln1_g, ln1_b, h);
    // 2) fused QKV projection: [4096,1024] @ [1024,3072]
    mma_gemm<0><<<dim3(QKVN / 128, ROWS / 128), 128, GSMEM>>>(h, wqkvt, nullptr, nullptr, qkv, ROWS, QKVN, DD);
    // 2b) V transpose per head (from fused buffer)
    vtrans_kernel<<<dim3(TT / 32, HD / 32, BB * HH), 256>>>(qkv, vt);
    // 3) attention (tensor core)
    attn_kernel<<<dim3(TT / 64, HH, BB), 128, ATTN_SMEM>>>(qkv, vt, mbits, attn);
    // 4) Wo + bias + residual(x)
    dim3 g1024(DD / 128, ROWS / 128);
    mma_gemm<2><<<g1024, 128, GSMEM>>>(attn, wot, bo, x, xmid, ROWS, DD, DD);
    // 5) LN2
    ln_kernel<<<ROWS, 256>>>(xmid, ln2_g, ln2_b, h2);
    // 6) FFN up + GELU
    mma_gemm<3><<<dim3(FF / 128, ROWS / 128), 128, GSMEM>>>(h2, w1t, b1, nullptr, ff, ROWS, FF, DD);
    // 7) FFN down + bias + residual(xmid) -> out
    mma_gemm<2><<<g1024, 128, GSMEM>>>(ff, w2t, b2, xmid, out, ROWS, DD, FF);
}

// round 13
// speedup vs baseline: 3.2056x; 1.0382x over previous
#include <cuda_runtime.h>
#include <math.h>
#include <stdint.h>

// ---------------- problem constants ----------------
#define BB 2
#define TT 2048
#define DD 1024
#define HH 16
#define HD 64
#define FF 4096
#define ROWS (BB * TT)          // 4096
#define LN_EPS 1e-5f
#define QKVN (3 * DD)           // 3072

// ---------------- scratch (__device__ globals; no allocation) ----------------
__device__ float g_h[ROWS * DD];
__device__ float g_qkv[ROWS * QKVN];        // fused Q|K|V, row stride 3072
__device__ float g_vt[BB * HH * HD * TT];   // [b,h][d][t]
__device__ float g_attn[ROWS * DD];
__device__ float g_xmid[ROWS * DD];
__device__ float g_h2[ROWS * DD];
__device__ float g_ff[ROWS * FF];
__device__ unsigned long long g_mask_bits[TT * (TT / 64)];
__device__ float g_wqkvt[QKVN * DD];
__device__ float g_wot[DD * DD];
__device__ float g_w1t[FF * DD];
__device__ float g_w2t[DD * FF];

// ---------------- helpers ----------------
__device__ __forceinline__ uint32_t f2tf32(float f) {
    uint32_t r;
    asm("cvt.rna.tf32.f32 %0, %1;" : "=r"(r) : "f"(f));
    return r;
}
__device__ __forceinline__ float gelu_exact(float x) {
    return 0.5f * x * (1.0f + erff(x * 0.70710678118654752f));
}
__device__ __forceinline__ void mma_tf32(float c[4], uint32_t a0, uint32_t a1,
                                         uint32_t a2, uint32_t a3,
                                         uint32_t b0, uint32_t b1) {
    asm volatile(
        "mma.sync.aligned.m16n8k8.row.col.f32.tf32.tf32.f32 "
        "{%0,%1,%2,%3}, {%4,%5,%6,%7}, {%8,%9}, {%0,%1,%2,%3};"
        : "+f"(c[0]), "+f"(c[1]), "+f"(c[2]), "+f"(c[3])
        : "r"(a0), "r"(a1), "r"(a2), "r"(a3), "r"(b0), "r"(b1));
}
__device__ __forceinline__ void ldsm_x4(uint32_t& r0, uint32_t& r1,
                                        uint32_t& r2, uint32_t& r3, uint32_t addr) {
    asm volatile("ldmatrix.sync.aligned.m8n8.x4.shared.b16 {%0,%1,%2,%3}, [%4];"
                 : "=r"(r0), "=r"(r1), "=r"(r2), "=r"(r3) : "r"(addr));
}
__device__ __forceinline__ void cp_async16(uint32_t saddr, const float* gaddr) {
    asm volatile("cp.async.cg.shared.global [%0], [%1], 16;" :: "r"(saddr), "l"(gaddr));
}
#define CP_COMMIT() asm volatile("cp.async.commit_group;" ::: "memory")
#define CP_WAIT1() asm volatile("cp.async.wait_group 1;" ::: "memory")
#define CP_WAIT0() asm volatile("cp.async.wait_group 0;" ::: "memory")
__device__ __forceinline__ void sts64(uint32_t addr, float a, float b) {
    asm volatile("st.shared.v2.f32 [%0], {%1,%2};" :: "r"(addr), "f"(a), "f"(b));
}

// ---------------- fused prepass: LN1 + 6 weight transposes + mask bits ----------------
// One launch; blocks dispatch on blockIdx.x ranges. All segments independent.
//  [0,4096)        LN1 rows
//  [4096,8192)     transpose4: z = (bid>>10), 32x32 tile = bid&1023
//  [8192,12288)    W1^T tiles: bx = t%128, by = t/128  (src 1024x4096)
//  [12288,16384)   W2^T tiles: bx = t%32,  by = t/32   (src 4096x1024)
//  [16384,16640)   mask bits (256 words/block)
#define PRE_BLOCKS 16640

__device__ __forceinline__ void tr_tile(const float* __restrict__ src,
                                        float* __restrict__ dst,
                                        int R, int C, int bx, int by,
                                        float (*t)[33])
{
    int c0 = bx * 32, r0 = by * 32;
    int tx = threadIdx.x & 31, ty = threadIdx.x >> 5;
#pragma unroll
    for (int i = 0; i < 32; i += 8)
        t[ty + i][tx] = src[(size_t)(r0 + ty + i) * C + c0 + tx];
    __syncthreads();
#pragma unroll
    for (int i = 0; i < 32; i += 8)
        dst[(size_t)(c0 + ty + i) * R + r0 + tx] = __uint_as_float(f2tf32(t[tx][ty + i]));
}

__device__ __forceinline__ void ln_row(const float* __restrict__ x,
                                       const float* __restrict__ gam,
                                       const float* __restrict__ bet,
                                       float* __restrict__ out, int row,
                                       float* red)
{
    int t = threadIdx.x;
    const float* xr = x + (size_t)row * DD;
    float4 xv = *(const float4*)(xr + t * 4);
    float s = xv.x + xv.y + xv.z + xv.w;
#pragma unroll
    for (int o = 16; o; o >>= 1) s += __shfl_xor_sync(0xffffffffu, s, o);
    if ((t & 31) == 0) red[t >> 5] = s;
    __syncthreads();
    float mu = 0.f;
#pragma unroll
    for (int i = 0; i < 8; i++) mu += red[i];
    mu *= (1.0f / (float)DD);
    __syncthreads();
    float dx = xv.x - mu, dy = xv.y - mu, dz = xv.z - mu, dw = xv.w - mu;
    float s2 = dx * dx + dy * dy + dz * dz + dw * dw;
#pragma unroll
    for (int o = 16; o; o >>= 1) s2 += __shfl_xor_sync(0xffffffffu, s2, o);
    if ((t & 31) == 0) red[t >> 5] = s2;
    __syncthreads();
    float var = 0.f;
#pragma unroll
    for (int i = 0; i < 8; i++) var += red[i];
    var *= (1.0f / (float)DD);
    float inv = rsqrtf(var + LN_EPS);
    float4 gv = *(const float4*)(gam + t * 4);
    float4 bv = *(const float4*)(bet + t * 4);
    float4 o4;
    o4.x = dx * inv * gv.x + bv.x;
    o4.y = dy * inv * gv.y + bv.y;
    o4.z = dz * inv * gv.z + bv.z;
    o4.w = dw * inv * gv.w + bv.w;
    *(float4*)(out + (size_t)row * DD + t * 4) = o4;
}

__global__ __launch_bounds__(256) void prepass_kernel(
    const float* __restrict__ x,
    const float* __restrict__ ln1_g, const float* __restrict__ ln1_b,
    const float* __restrict__ Wq, const float* __restrict__ Wk,
    const float* __restrict__ Wv, const float* __restrict__ Wo,
    const float* __restrict__ W1, const float* __restrict__ W2,
    const unsigned char* __restrict__ mask_raw)
{
    __shared__ float sh[32][33];
    int bid = blockIdx.x;

    if (bid < 4096) {                       // LN1
        ln_row(x, ln1_g, ln1_b, g_h, bid, &sh[0][0]);
        return;
    }
    bid -= 4096;
    if (bid < 4096) {                       // Wq/Wk/Wv -> wqkvt, Wo -> wot
        int z = bid >> 10, tile = bid & 1023;
        const float* src = (z == 0) ? Wq : (z == 1) ? Wk : (z == 2) ? Wv : Wo;
        float* dst = (z < 3) ? (g_wqkvt + (size_t)z * DD * DD) : g_wot;
        tr_tile(src, dst, DD, DD, tile & 31, tile >> 5, sh);
        return;
    }
    bid -= 4096;
    if (bid < 4096) {                       // W1 (1024x4096) -> w1t (4096x1024)
        tr_tile(W1, g_w1t, DD, FF, bid & 127, bid >> 7, sh);
        return;
    }
    bid -= 4096;
    if (bid < 4096) {                       // W2 (4096x1024) -> w2t (1024x4096)
        tr_tile(W2, g_w2t, FF, DD, bid & 31, bid >> 5, sh);
        return;
    }
    bid -= 4096;
    {                                       // mask bits
        int i = bid * 256 + threadIdx.x;    // word index < TT*32
        int row = i >> 5, w = i & 31;
        bool one_byte = (mask_raw[2048] != 0);
        unsigned long long bits = 0ull;
        if (one_byte) {
            const unsigned char* p = mask_raw + (size_t)row * TT + w * 64;
#pragma unroll 8
            for (int j = 0; j < 64; j++) if (p[j]) bits |= 1ull << j;
        } else {
            const unsigned int* p = (const unsigned int*)mask_raw + (size_t)row * TT + w * 64;
#pragma unroll 8
            for (int j = 0; j < 64; j++) if (p[j]) bits |= 1ull << j;
        }
        g_mask_bits[i] = bits;
    }
}

// ---------------- V transpose per head ----------------
__global__ __launch_bounds__(256) void vtrans_kernel(const float* __restrict__ qkv,
                                                     float* __restrict__ vt)
{
    __shared__ float tsh[32][33];
    int bh = blockIdx.z;
    int b = bh >> 4, h = bh & 15;
    int t0 = blockIdx.x * 32, d0 = blockIdx.y * 32;
    int tx = threadIdx.x & 31, ty = threadIdx.x >> 5;
    const float* src = qkv + (size_t)b * TT * QKVN + 2048 + (size_t)h * HD;
#pragma unroll
    for (int i = 0; i < 32; i += 8)
        tsh[ty + i][tx] = src[(size_t)(t0 + ty + i) * QKVN + d0 + tx];
    __syncthreads();
    float* dst = vt + ((size_t)bh * HD + d0) * TT + t0;
#pragma unroll
    for (int i = 0; i < 32; i += 8)
        dst[(size_t)(ty + i) * TT + tx] = tsh[tx][ty + i];
}

// ---------------- LayerNorm (standalone, for LN2) ----------------
__global__ __launch_bounds__(256) void ln_kernel(const float* __restrict__ x,
                                                 const float* __restrict__ gam,
                                                 const float* __restrict__ bet,
                                                 float* __restrict__ out)
{
    __shared__ float red[8];
    ln_row(x, gam, bet, out, blockIdx.x, red);
}

// ---------------- tf32 mma.sync GEMM ----------------
#define GSTAGE 32768
#define GSMEM  (3 * GSTAGE)

template<int EPI>
__global__ __launch_bounds__(128, 2) void mma_gemm(
    const float* __restrict__ A, const float* __restrict__ Bt,
    const float* __restrict__ bias, const float* __restrict__ resid,
    float* __restrict__ C, int M, int N, int K)
{
    extern __shared__ unsigned char smem_raw[];
    const uint32_t sbase = (uint32_t)__cvta_generic_to_shared(smem_raw);
    const int tid = threadIdx.x;
    const int wid = tid >> 5, lane = tid & 31;
    const int wm = wid & 1, wn = wid >> 1;
    const int g = lane >> 2, t = lane & 3;
    const int mb = blockIdx.y, nb = blockIdx.x;

    const int rl = tid >> 3;
    const int ch = tid & 7;
    const uint32_t sw16 = (uint32_t)((ch ^ (rl & 7)) * 16);
    const float* Ag = A + (size_t)(mb * 128 + rl) * K + ch * 4;
    const float* Bg = Bt + (size_t)(nb * 128 + rl) * K + ch * 4;

    const int l7 = lane & 7, mat = lane >> 3;
    const uint32_t a_rp = (uint32_t)((l7 + (mat & 1) * 8) * 128);
    const int a_ca = mat >> 1;
    const uint32_t b_rp = (uint32_t)((l7 + (mat >> 1) * 8) * 128);
    const int b_ca = mat & 1;

    float acc[4][8][4];
#pragma unroll
    for (int i = 0; i < 4; i++)
#pragma unroll
        for (int j = 0; j < 8; j++)
#pragma unroll
            for (int r = 0; r < 4; r++) acc[i][j][r] = 0.f;

    const int NC = K / 32;

    auto issue = [&](int cc, int s) {
        const uint32_t ab = sbase + (uint32_t)s * GSTAGE;
        const size_t ko = (size_t)cc * 32;
#pragma unroll
        for (int p = 0; p < 8; p++) {
            uint32_t soff = (uint32_t)((p * 16 + rl) * 128) + sw16;
            cp_async16(ab + soff,          Ag + (size_t)(p * 16) * K + ko);
            cp_async16(ab + 16384u + soff, Bg + (size_t)(p * 16) * K + ko);
        }
        CP_COMMIT();
    };

    issue(0, 0);
    issue(1, 1);

    uint32_t af[2][4][4], bf[2][8][2];

    for (int c = 0; c < NC; c++) {
        if (c < NC - 1) { CP_WAIT1(); } else { CP_WAIT0(); }
        __syncthreads();
        if (c + 2 < NC) issue(c + 2, (c + 2) % 3);

        const uint32_t sa = sbase + (uint32_t)(c % 3) * GSTAGE;
        const uint32_t sb = sa + 16384u;

        auto load_frags = [&](int ks, uint32_t (*afd)[4], uint32_t (*bfd)[2]) {
            const int c0 = ks * 2;
#pragma unroll
            for (int mt = 0; mt < 4; mt++) {
                uint32_t addr = sa + (uint32_t)((wm * 64 + mt * 16) * 128) + a_rp
                              + (uint32_t)(((c0 + a_ca) ^ l7) * 16);
                ldsm_x4(afd[mt][0], afd[mt][1], afd[mt][2], afd[mt][3], addr);
            }
#pragma unroll
            for (int pr = 0; pr < 4; pr++) {
                uint32_t addr = sb + (uint32_t)((wn * 64 + pr * 16) * 128) + b_rp
                              + (uint32_t)(((c0 + b_ca) ^ l7) * 16);
                ldsm_x4(bfd[2 * pr][0], bfd[2 * pr][1], bfd[2 * pr + 1][0], bfd[2 * pr + 1][1], addr);
            }
        };

        load_frags(0, af[0], bf[0]);
#pragma unroll
        for (int ks = 0; ks < 4; ks++) {
            const int cur = ks & 1;
            if (ks < 3) load_frags(ks + 1, af[cur ^ 1], bf[cur ^ 1]);
#pragma unroll
            for (int mt = 0; mt < 4; mt++)
#pragma unroll
                for (int nt = 0; nt < 8; nt++)
                    mma_tf32(acc[mt][nt], af[cur][mt][0], af[cur][mt][1],
                             af[cur][mt][2], af[cur][mt][3],
                             bf[cur][nt][0], bf[cur][nt][1]);
        }
    }

#pragma unroll
    for (int mt = 0; mt < 4; mt++) {
        int row0 = mb * 128 + wm * 64 + mt * 16 + g;
#pragma unroll
        for (int nt = 0; nt < 8; nt++) {
            int col = nb * 128 + wn * 64 + nt * 8 + 2 * t;
#pragma unroll
            for (int half = 0; half < 2; half++) {
                int row = row0 + half * 8;
                float v0 = acc[mt][nt][half * 2 + 0];
                float v1 = acc[mt][nt][half * 2 + 1];
                if (EPI >= 1) { v0 += bias[col]; v1 += bias[col + 1]; }
                if (EPI == 3) { v0 = gelu_exact(v0); v1 = gelu_exact(v1); }
                if (EPI == 2) {
                    const float* rp = resid + (size_t)row * N + col;
                    v0 += rp[0]; v1 += rp[1];
                }
                float2 o2; o2.x = v0; o2.y = v1;
                *(float2*)(C + (size_t)row * N + col) = o2;
            }
        }
    }
}

// ---------------- tensor-core flash attention, q-tile 128 ----------------
#define AQ_OFF 0
#define AK_OFF 32768
#define AV_OFF 65536
#define AP_OFF 98304
#define ATTN_SMEM 131072

__global__ __launch_bounds__(256, 1) void attn_kernel(
    const float* __restrict__ QKV, const float* __restrict__ Vt,
    const unsigned long long* __restrict__ mbits, float* __restrict__ O)
{
    extern __shared__ unsigned char sm_raw[];
    const uint32_t sb = (uint32_t)__cvta_generic_to_shared(sm_raw);
    const int tid = threadIdx.x;
    const int wid = tid >> 5, lane = tid & 31;
    const int l7 = lane & 7, mat = lane >> 3;
    const int g = lane >> 2, t = lane & 3;
    const int qb = blockIdx.x, h = blockIdx.y, b = blockIdx.z;
    const int q0 = qb * 128;

    const float* qg = QKV + (size_t)b * TT * QKVN + (size_t)h * HD;
    const float* kg = QKV + (size_t)b * TT * QKVN + 1024 + (size_t)h * HD;
    const float* vtg = Vt + (size_t)(b * HH + h) * HD * TT;

    const int crowQ = tid >> 1, chalfQ = (tid & 1) * 8;
    const uint32_t cswQ = (uint32_t)(crowQ & 7);
    const int crowK = tid >> 2, cqK = (tid & 3) * 4;
    const uint32_t cswK = (uint32_t)(crowK & 7);

    {
#pragma unroll
        for (int i = 0; i < 8; i++) {
            int cc = chalfQ + i;
            uint32_t sa = sb + AQ_OFF + (uint32_t)((cc >> 3) * 16384 + crowQ * 128)
                        + (uint32_t)((((uint32_t)(cc & 7)) ^ cswQ) * 16);
            cp_async16(sa, qg + (size_t)(q0 + crowQ) * QKVN + cc * 4);
        }
    }
    auto ld_k = [&](uint32_t dst, int tok0) {
#pragma unroll
        for (int i = 0; i < 4; i++) {
            int cc = cqK + i;
            uint32_t sa = dst + (uint32_t)((cc >> 3) * 8192 + crowK * 128)
                        + (uint32_t)((((uint32_t)(cc & 7)) ^ cswK) * 16);
            cp_async16(sa, kg + (size_t)(tok0 + crowK) * QKVN + cc * 4);
        }
    };
    auto ld_v = [&](uint32_t dst, int k0) {
#pragma unroll
        for (int i = 0; i < 4; i++) {
            int cc = cqK + i;
            uint32_t sa = dst + (uint32_t)((cc >> 3) * 8192 + crowK * 128)
                        + (uint32_t)((((uint32_t)(cc & 7)) ^ cswK) * 16);
            cp_async16(sa, vtg + (size_t)crowK * TT + k0 + cc * 4);
        }
    };

    ld_k(sb + AK_OFF, 0);
    ld_v(sb + AV_OFF, 0);
    CP_COMMIT();

    float m0 = -INFINITY, m1 = -INFINITY, le0 = 0.f, le1 = 0.f;
    float oacc[8][4];
#pragma unroll
    for (int j = 0; j < 8; j++)
#pragma unroll
        for (int r = 0; r < 4; r++) oacc[j][r] = 0.f;

    const uint32_t a_rp = (uint32_t)((wid * 16 + l7 + (mat & 1) * 8) * 128);
    const int a_ca = mat >> 1;
    const uint32_t b_rp = (uint32_t)((l7 + (mat >> 1) * 8) * 128);
    const int b_ca = mat & 1;
    const int rowq0 = q0 + wid * 16 + g;
    const int rmax = q0 + wid * 16 + 15;
    const int kmax = 2 * qb + 1;

    for (int kb = 0; kb <= kmax; kb++) {
        CP_WAIT0();
        __syncthreads();
        const int s = kb & 1;
        if (kb < kmax) {
            ld_k(sb + AK_OFF + (s ^ 1) * 16384, (kb + 1) * 64);
            ld_v(sb + AV_OFF + (s ^ 1) * 16384, (kb + 1) * 64);
            CP_COMMIT();
        }
        if (kb * 64 > rmax) continue;      // warp-uniform causal skip
        const uint32_t ksm = sb + AK_OFF + s * 16384;
        const uint32_t vsm = sb + AV_OFF + s * 16384;

        // ---- S = Q K^T ----
        float sacc[8][4];
#pragma unroll
        for (int j = 0; j < 8; j++)
#pragma unroll
            for (int r = 0; r < 4; r++) sacc[j][r] = 0.f;
#pragma unroll
        for (int ks = 0; ks < 8; ks++) {
            const int c0 = ks * 2;
            uint32_t a0, a1, a2, a3;
            {
                int cc = c0 + a_ca;
                uint32_t addr = sb + AQ_OFF + (uint32_t)((cc >> 3) * 16384) + a_rp
                              + (uint32_t)((((uint32_t)(cc & 7)) ^ (uint32_t)l7) * 16);
                ldsm_x4(a0, a1, a2, a3, addr);
            }
            uint32_t bf[8][2];
#pragma unroll
            for (int pr = 0; pr < 4; pr++) {
                int cc = c0 + b_ca;
                uint32_t addr = ksm + (uint32_t)((cc >> 3) * 8192) + (uint32_t)(pr * 16 * 128)
                              + b_rp + (uint32_t)((((uint32_t)(cc & 7)) ^ (uint32_t)l7) * 16);
                ldsm_x4(bf[2 * pr][0], bf[2 * pr][1], bf[2 * pr + 1][0], bf[2 * pr + 1][1], addr);
            }
#pragma unroll
            for (int nt = 0; nt < 8; nt++)
                mma_tf32(sacc[nt], a0, a1, a2, a3, bf[nt][0], bf[nt][1]);
        }

        // ---- mask + scale + online softmax ----
        unsigned long long w0 = mbits[(size_t)rowq0 * 32 + kb];
        unsigned long long w1 = mbits[(size_t)(rowq0 + 8) * 32 + kb];
        float tm0 = -INFINITY, tm1 = -INFINITY;
#pragma unroll
        for (int nt = 0; nt < 8; nt++) {
            int col = nt * 8 + 2 * t;
            sacc[nt][0] = ((w0 >> col) & 1ull) ? sacc[nt][0] * 0.125f : -1e9f;
            sacc[nt][1] = ((w0 >> (col + 1)) & 1ull) ? sacc[nt][1] * 0.125f : -1e9f;
            sacc[nt][2] = ((w1 >> col) & 1ull) ? sacc[nt][2] * 0.125f : -1e9f;
            sacc[nt][3] = ((w1 >> (col + 1)) & 1ull) ? sacc[nt][3] * 0.125f : -1e9f;
            tm0 = fmaxf(tm0, fmaxf(sacc[nt][0], sacc[nt][1]));
            tm1 = fmaxf(tm1, fmaxf(sacc[nt][2], sacc[nt][3]));
        }
#pragma unroll
        for (int o = 1; o <= 2; o <<= 1) {
            tm0 = fmaxf(tm0, __shfl_xor_sync(0xffffffffu, tm0, o));
            tm1 = fmaxf(tm1, __shfl_xor_sync(0xffffffffu, tm1, o));
        }
        float mn0 = fmaxf(m0, tm0), mn1 = fmaxf(m1, tm1);
        float al0 = __expf(m0 - mn0), al1 = __expf(m1 - mn1);
        m0 = mn0; m1 = mn1;
        float rs0 = 0.f, rs1 = 0.f;
#pragma unroll
        for (int nt = 0; nt < 8; nt++) {
            float p0 = __expf(sacc[nt][0] - mn0);
            float p1 = __expf(sacc[nt][1] - mn0);
            float p2 = __expf(sacc[nt][2] - mn1);
            float p3 = __expf(sacc[nt][3] - mn1);
            rs0 += p0 + p1; rs1 += p2 + p3;
            int cp = nt * 8 + 2 * t;
            int cc = cp >> 2;
            uint32_t base = sb + AP_OFF + (uint32_t)((cc >> 3) * 16384)
                          + (uint32_t)((((uint32_t)(cc & 7)) ^ (uint32_t)g) * 16)
                          + (uint32_t)((cp & 3) * 4);
            sts64(base + (uint32_t)((wid * 16 + g) * 128), p0, p1);
            sts64(base + (uint32_t)((wid * 16 + g + 8) * 128), p2, p3);
        }
#pragma unroll
        for (int o = 1; o <= 2; o <<= 1) {
            rs0 += __shfl_xor_sync(0xffffffffu, rs0, o);
            rs1 += __shfl_xor_sync(0xffffffffu, rs1, o);
        }
        le0 = le0 * al0 + rs0;
        le1 = le1 * al1 + rs1;
#pragma unroll
        for (int nt = 0; nt < 8; nt++) {
            oacc[nt][0] *= al0; oacc[nt][1] *= al0;
            oacc[nt][2] *= al1; oacc[nt][3] *= al1;
        }
        __syncwarp(0xffffffffu);   // P rows are warp-private

        // ---- O += P V ----
#pragma unroll
        for (int ks = 0; ks < 8; ks++) {
            const int c0 = ks * 2;
            uint32_t a0, a1, a2, a3;
            {
                int cc = c0 + a_ca;
                uint32_t addr = sb + AP_OFF + (uint32_t)((cc >> 3) * 16384) + a_rp
                              + (uint32_t)((((uint32_t)(cc & 7)) ^ (uint32_t)l7) * 16);
                ldsm_x4(a0, a1, a2, a3, addr);
            }
            uint32_t bf[8][2];
#pragma unroll
            for (int pr = 0; pr < 4; pr++) {
                int cc = c0 + b_ca;
                uint32_t addr = vsm + (uint32_t)((cc >> 3) * 8192) + (uint32_t)(pr * 16 * 128)
                              + b_rp + (uint32_t)((((uint32_t)(cc & 7)) ^ (uint32_t)l7) * 16);
                ldsm_x4(bf[2 * pr][0], bf[2 * pr][1], bf[2 * pr + 1][0], bf[2 * pr + 1][1], addr);
            }
#pragma unroll
            for (int nt = 0; nt < 8; nt++)
                mma_tf32(oacc[nt], a0, a1, a2, a3, bf[nt][0], bf[nt][1]);
        }
    }

    // ---- normalize + write ----
    float inv0 = 1.0f / le0, inv1 = 1.0f / le1;
    float* ob = O + (size_t)b * TT * DD + (size_t)h * HD;
#pragma unroll
    for (int nt = 0; nt < 8; nt++) {
        int col = nt * 8 + 2 * t;
        float2 o2;
        o2.x = oacc[nt][0] * inv0; o2.y = oacc[nt][1] * inv0;
        *(float2*)(ob + (size_t)rowq0 * DD + col) = o2;
        o2.x = oacc[nt][2] * inv1; o2.y = oacc[nt][3] * inv1;
        *(float2*)(ob + (size_t)(rowq0 + 8) * DD + col) = o2;
    }
}

// ---------------- launch ----------------
extern "C" void kernel_launch(void* const* d_in, const int* in_sizes, int n_in,
                              void* d_out, int out_size)
{
    (void)in_sizes; (void)n_in; (void)out_size;
    const float* x     = (const float*)d_in[0];
    const unsigned char* mask_raw = (const unsigned char*)d_in[1];
    const float* ln1_g = (const float*)d_in[2];
    const float* ln1_b = (const float*)d_in[3];
    const float* ln2_g = (const float*)d_in[4];
    const float* ln2_b = (const float*)d_in[5];
    const float* Wq    = (const float*)d_in[6];
    const float* Wk    = (const float*)d_in[7];
    const float* Wv    = (const float*)d_in[8];
    const float* Wo    = (const float*)d_in[9];
    const float* bo    = (const float*)d_in[10];
    const float* W1    = (const float*)d_in[11];
    const float* b1    = (const float*)d_in[12];
    const float* W2    = (const float*)d_in[13];
    const float* b2    = (const float*)d_in[14];
    float* out = (float*)d_out;

    float *h, *qkv, *vt, *attn, *xmid, *h2, *ff;
    float *wqkvt, *wot, *w1t, *w2t;
    unsigned long long* mbits;
    cudaGetSymbolAddress((void**)&h,     g_h);
    cudaGetSymbolAddress((void**)&qkv,   g_qkv);
    cudaGetSymbolAddress((void**)&vt,    g_vt);
    cudaGetSymbolAddress((void**)&attn,  g_attn);
    cudaGetSymbolAddress((void**)&xmid,  g_xmid);
    cudaGetSymbolAddress((void**)&h2,    g_h2);
    cudaGetSymbolAddress((void**)&ff,    g_ff);
    cudaGetSymbolAddress((void**)&wqkvt, g_wqkvt);
    cudaGetSymbolAddress((void**)&wot,   g_wot);
    cudaGetSymbolAddress((void**)&w1t,   g_w1t);
    cudaGetSymbolAddress((void**)&w2t,   g_w2t);
    cudaGetSymbolAddress((void**)&mbits, g_mask_bits);

    cudaFuncSetAttribute(attn_kernel, cudaFuncAttributeMaxDynamicSharedMemorySize, ATTN_SMEM);
    cudaFuncSetAttribute(mma_gemm<0>, cudaFuncAttributeMaxDynamicSharedMemorySize, GSMEM);
    cudaFuncSetAttribute(mma_gemm<2>, cudaFuncAttributeMaxDynamicSharedMemorySize, GSMEM);
    cudaFuncSetAttribute(mma_gemm<3>, cudaFuncAttributeMaxDynamicSharedMemorySize, GSMEM);

    // 0) fused prepass: LN1 + all weight transposes + mask bits (one launch)
    prepass_kernel<<<PRE_BLOCKS, 256>>>(x, ln1_g, ln1_b, Wq, Wk, Wv, Wo, W1, W2, mask_raw);
    // 1) fused QKV projection: [4096,1024] @ [1024,3072]
    mma_gemm<0><<<dim3(QKVN / 128, ROWS / 128), 128, GSMEM>>>(h, wqkvt, nullptr, nullptr, qkv, ROWS, QKVN, DD);
    // 1b) V transpose per head
    vtrans_kernel<<<dim3(TT / 32, HD / 32, BB * HH), 256>>>(qkv, vt);
    // 2) attention (tensor core, 128-row q-tiles)
    attn_kernel<<<dim3(TT / 128, HH, BB), 256, ATTN_SMEM>>>(qkv, vt, mbits, attn);
    // 3) Wo + bias + residual(x)
    dim3 g1024(DD / 128, ROWS / 128);
    mma_gemm<2><<<g1024, 128, GSMEM>>>(attn, wot, bo, x, xmid, ROWS, DD, DD);
    // 4) LN2
    ln_kernel<<<ROWS, 256>>>(xmid, ln2_g, ln2_b, h2);
    // 5) FFN up + GELU
    mma_gemm<3><<<dim3(FF / 128, ROWS / 128), 128, GSMEM>>>(h2, w1t, b1, nullptr, ff, ROWS, FF, DD);
    // 6) FFN down + bias + residual(xmid) -> out
    mma_gemm<2><<<g1024, 128, GSMEM>>>(ff, w2t, b2, xmid, out, ROWS, DD, FF);
}